// round 1
// baseline (speedup 1.0000x reference)
#include <cuda_runtime.h>
#include <math.h>

#define BB 4
#define SEQ 4096
#define DIM 256
#define CHK 128
#define NCH (SEQ/CHK)      // 32
#define GAMMA 0.9865f
#define INV16 0.0625f

// ---------------- scratch (device globals; no allocation) ----------------
__device__ float g_Q[BB*SEQ*DIM];           // 16 MB
__device__ float g_K[BB*SEQ*DIM];           // 16 MB
__device__ float g_V[BB*SEQ*DIM];           // 16 MB
__device__ float g_ic[SEQ];                 // 1/sqrt(c_j)
__device__ float g_sloc[BB*NCH*DIM];
__device__ float g_sbd [BB*NCH*DIM];
__device__ float g_dinv[BB*SEQ];            // 1/denom
__device__ float g_T[(size_t)BB*NCH*DIM*DIM];   // 33.5 MB, local T then in-place prefix

// ---------------- K0: column normalizer ic[j] = 1/sqrt(sum_k D[j,k]) -----
__global__ void k_init() {
    int j = blockIdx.x*256 + threadIdx.x;
    if (j < SEQ) {
        float lg = logf(GAMMA);
        float gp = expf((float)(j+1)*lg);             // gamma^(j+1)
        g_ic[j] = rsqrtf((1.0f - gp)/(1.0f - GAMMA)); // c_j = (1-g^(j+1))/(1-g)
    }
}

// ---------------- K1: Q/K/V projections  [16384,256]@[256,256]+b ---------
__global__ void __launch_bounds__(256) k_proj(
    const float* __restrict__ xq, const float* __restrict__ xk, const float* __restrict__ xv,
    const float* __restrict__ Wq, const float* __restrict__ bq,
    const float* __restrict__ Wk, const float* __restrict__ bk,
    const float* __restrict__ Wv, const float* __restrict__ bv)
{
    __shared__ float Xs[64*33];
    __shared__ float Ws[32*64];
    const float *X, *W, *bias; float* O;
    int m = blockIdx.z;
    if (m == 0)      { X = xq; W = Wq; bias = bq; O = g_Q; }
    else if (m == 1) { X = xk; W = Wk; bias = bk; O = g_K; }
    else             { X = xv; W = Wv; bias = bv; O = g_V; }

    int tid = threadIdx.x;
    int tx = tid & 15, ty = tid >> 4;
    int r0 = blockIdx.x * 64;
    int c0 = blockIdx.y * 64;
    float acc[4][4] = {};

    for (int e0 = 0; e0 < DIM; e0 += 32) {
        #pragma unroll
        for (int l = 0; l < 2; l++) {
            int idx = tid + l*256;                 // 0..511
            int row = idx >> 3, c4 = (idx & 7)*4;  // 64 x 32
            float4 v = *(const float4*)&X[(size_t)(r0+row)*DIM + e0 + c4];
            Xs[row*33+c4+0]=v.x; Xs[row*33+c4+1]=v.y; Xs[row*33+c4+2]=v.z; Xs[row*33+c4+3]=v.w;
        }
        #pragma unroll
        for (int l = 0; l < 2; l++) {
            int idx = tid + l*256;
            int row = idx >> 4, c4 = (idx & 15)*4; // 32 x 64
            *(float4*)&Ws[row*64 + c4] = *(const float4*)&W[(size_t)(e0+row)*DIM + c0 + c4];
        }
        __syncthreads();
        #pragma unroll
        for (int e = 0; e < 32; e++) {
            float a[4];
            #pragma unroll
            for (int ii=0; ii<4; ii++) a[ii] = Xs[(ty*4+ii)*33 + e];
            float4 b4 = *(const float4*)&Ws[e*64 + tx*4];
            float bb[4] = {b4.x, b4.y, b4.z, b4.w};
            #pragma unroll
            for (int ii=0; ii<4; ii++)
                #pragma unroll
                for (int jj=0; jj<4; jj++) acc[ii][jj] += a[ii]*bb[jj];
        }
        __syncthreads();
    }
    float4 b4 = *(const float4*)&bias[c0 + tx*4];
    float bb[4] = {b4.x, b4.y, b4.z, b4.w};
    #pragma unroll
    for (int ii=0; ii<4; ii++) {
        int r = r0 + ty*4 + ii;
        float4 o;
        o.x = acc[ii][0]+bb[0]; o.y = acc[ii][1]+bb[1];
        o.z = acc[ii][2]+bb[2]; o.w = acc[ii][3]+bb[3];
        *(float4*)&O[(size_t)r*DIM + c0 + tx*4] = o;
    }
}

// ---------------- K2: per-chunk local decayed K/sqrt(c) sum --------------
__global__ void k_sloc() {
    int blk = blockIdx.x; int b = blk/NCH; int c = blk%NCH; int c0 = c*CHK;
    int d = threadIdx.x;
    float s = 0.f;
    for (int j = 0; j < CHK; j++) {
        int gj = c0 + j;
        s = s*GAMMA + g_K[(size_t)(b*SEQ+gj)*DIM + d]*g_ic[gj];
    }
    g_sloc[blk*DIM + d] = s;
}

// ---------------- K3: prefix combine s across chunks ---------------------
__global__ void k_spref() {
    int b = blockIdx.x; int d = threadIdx.x;
    float gC = expf((float)CHK*logf(GAMMA));
    float s = 0.f;
    for (int c = 0; c < NCH; c++) {
        g_sbd[(b*NCH+c)*DIM + d] = s;              // state BEFORE chunk c
        s = s*gC + g_sloc[(b*NCH+c)*DIM + d];
    }
}

// ---------------- K4: r[b,j] = Q_j . S_j / 16 ;  denom_inv ---------------
__global__ void k_rdenom() {
    int blk = blockIdx.x; int b = blk/NCH; int c = blk%NCH; int c0 = c*CHK;
    int tid = threadIdx.x;
    int lane = tid & 31, wid = tid >> 5;
    __shared__ float red[8];
    float w = g_sbd[blk*DIM + tid];
    for (int j = 0; j < CHK; j++) {
        int gj = c0 + j;
        size_t p = (size_t)(b*SEQ + gj)*DIM + tid;
        w = w*GAMMA + g_K[p]*g_ic[gj];
        float pr = g_Q[p]*w;
        #pragma unroll
        for (int o = 16; o > 0; o >>= 1) pr += __shfl_xor_sync(0xffffffffu, pr, o);
        if (lane == 0) red[wid] = pr;
        __syncthreads();
        if (tid == 0) {
            float r = 0.f;
            #pragma unroll
            for (int k = 0; k < 8; k++) r += red[k];
            r *= INV16;
            g_dinv[b*SEQ + gj] = 1.0f / fmaxf(fabsf(r), 1.0f);
        }
        __syncthreads();
    }
}

// ---------------- K5: chunk-local T = sum_j w_j Khat_j V_j^T -------------
__global__ void __launch_bounds__(256) k_tloc() {
    __shared__ float Ks[32*64];
    __shared__ float Vs[32*64];
    __shared__ float gpw[CHK];
    int blk = blockIdx.x; int b = blk/NCH; int c = blk%NCH; int c0 = c*CHK;
    int tid = threadIdx.x;
    if (tid < CHK) gpw[tid] = expf((float)tid * logf(GAMMA));
    __syncthreads();
    int tx = tid & 15, ty = tid >> 4;
    int d1t = blockIdx.y * 64, d2t = blockIdx.z * 64;
    float acc[4][4] = {};
    for (int j0 = 0; j0 < CHK; j0 += 32) {
        #pragma unroll
        for (int l = 0; l < 2; l++) {
            int idx = tid + l*256;
            int row = idx >> 4, c4 = (idx & 15)*4;
            int gj = c0 + j0 + row;
            float w = gpw[CHK-1-(j0+row)] * g_ic[gj] * INV16 * g_dinv[b*SEQ + gj];
            float4 kv = *(const float4*)&g_K[(size_t)(b*SEQ+gj)*DIM + d1t + c4];
            kv.x*=w; kv.y*=w; kv.z*=w; kv.w*=w;
            *(float4*)&Ks[row*64 + c4] = kv;
            *(float4*)&Vs[row*64 + c4] = *(const float4*)&g_V[(size_t)(b*SEQ+gj)*DIM + d2t + c4];
        }
        __syncthreads();
        #pragma unroll
        for (int j = 0; j < 32; j++) {
            float a[4];
            #pragma unroll
            for (int ii=0; ii<4; ii++) a[ii] = Ks[j*64 + ty*4 + ii];
            float4 v4 = *(const float4*)&Vs[j*64 + tx*4];
            float bb[4] = {v4.x, v4.y, v4.z, v4.w};
            #pragma unroll
            for (int ii=0; ii<4; ii++)
                #pragma unroll
                for (int jj=0; jj<4; jj++) acc[ii][jj] += a[ii]*bb[jj];
        }
        __syncthreads();
    }
    #pragma unroll
    for (int ii=0; ii<4; ii++) {
        int d1 = d1t + ty*4 + ii;
        float4 o; o.x=acc[ii][0]; o.y=acc[ii][1]; o.z=acc[ii][2]; o.w=acc[ii][3];
        *(float4*)&g_T[((size_t)blk*DIM + d1)*DIM + d2t + tx*4] = o;
    }
}

// ---------------- K6: in-place prefix of T over chunks -------------------
__global__ void k_tpref() {
    int idx = blockIdx.x*256 + threadIdx.x;  // BB*DIM*DIM threads
    int b   = idx >> 16;                     // DIM*DIM = 65536
    int off = idx & 65535;
    float gC = expf((float)CHK * logf(GAMMA));
    float t = 0.f;
    for (int c = 0; c < NCH; c++) {
        size_t p = (((size_t)(b*NCH + c)) << 16) + off;
        float lc = g_T[p];
        g_T[p] = t;                          // state BEFORE chunk c
        t = t*gC + lc;
    }
}

// ---------------- K7: fused output per chunk -----------------------------
// out_i = sum_{k<=i in chunk} g^{i-k} (Q_i.K_k) colw_k V_k  +  g^{i+1} Q_i @ T_bd
__global__ void __launch_bounds__(256) k_out(float* __restrict__ out) {
    extern __shared__ float sm[];
    float* Asm = sm;                 // [128][133]
    float* St  = sm + 128*133;       // staging, 8448 floats
    __shared__ float gpw[CHK];
    __shared__ float colw[CHK];
    int blk = blockIdx.x; int b = blk/NCH; int c = blk%NCH; int c0 = c*CHK;
    int tid = threadIdx.x; int tx = tid & 15, ty = tid >> 4;
    if (tid < CHK) {
        gpw[tid] = expf((float)tid * logf(GAMMA));
        int gj = c0 + tid;
        colw[tid] = g_ic[gj]*INV16*g_dinv[b*SEQ + gj];
    }
    __syncthreads();

    // ---- Phase A: A = Q_chunk @ K_chunk^T (128x128, k=256) ----
    {
        float acc[8][8] = {};
        float* Qs = St;              // [128][33]
        float* Ks = St + 128*33;
        for (int e0 = 0; e0 < DIM; e0 += 32) {
            #pragma unroll
            for (int l = 0; l < 4; l++) {
                int idx = tid + l*256;
                int row = idx >> 3, c4 = (idx & 7)*4;
                size_t p = (size_t)(b*SEQ+c0+row)*DIM + e0 + c4;
                float4 q = *(const float4*)&g_Q[p];
                Qs[row*33+c4+0]=q.x; Qs[row*33+c4+1]=q.y; Qs[row*33+c4+2]=q.z; Qs[row*33+c4+3]=q.w;
                float4 k4 = *(const float4*)&g_K[p];
                Ks[row*33+c4+0]=k4.x; Ks[row*33+c4+1]=k4.y; Ks[row*33+c4+2]=k4.z; Ks[row*33+c4+3]=k4.w;
            }
            __syncthreads();
            #pragma unroll
            for (int e = 0; e < 32; e++) {
                float a[8], bb[8];
                #pragma unroll
                for (int ii=0; ii<8; ii++) a[ii]  = Qs[(ty*8+ii)*33 + e];
                #pragma unroll
                for (int kk=0; kk<8; kk++) bb[kk] = Ks[(tx*8+kk)*33 + e];
                #pragma unroll
                for (int ii=0; ii<8; ii++)
                    #pragma unroll
                    for (int kk=0; kk<8; kk++) acc[ii][kk] += a[ii]*bb[kk];
            }
            __syncthreads();
        }
        #pragma unroll
        for (int ii=0; ii<8; ii++) {
            int i = ty*8+ii;
            #pragma unroll
            for (int kk=0; kk<8; kk++) {
                int k = tx*8+kk;
                float v = (i >= k) ? acc[ii][kk]*gpw[i-k]*colw[k] : 0.0f;
                Asm[i*133 + k] = v;
            }
        }
        __syncthreads();
    }

    // ---- Phase B: out = Asm @ V  +  g^{i+1} * (Q @ T_bd), 64-col tiles ----
    for (int d0 = 0; d0 < DIM; d0 += 64) {
        float acc1[8][4] = {};
        float acc2[8][4] = {};
        {   // pass 1: Asm(128x128) @ V_chunk(128x64)
            float* Vs = St;          // [32][68]
            for (int k0 = 0; k0 < CHK; k0 += 32) {
                #pragma unroll
                for (int l = 0; l < 2; l++) {
                    int idx = tid + l*256;
                    int row = idx >> 4, c4 = (idx & 15)*4;
                    *(float4*)&Vs[row*68 + c4] =
                        *(const float4*)&g_V[(size_t)(b*SEQ+c0+k0+row)*DIM + d0 + c4];
                }
                __syncthreads();
                #pragma unroll
                for (int k = 0; k < 32; k++) {
                    float a[8];
                    #pragma unroll
                    for (int ii=0; ii<8; ii++) a[ii] = Asm[(ty*8+ii)*133 + k0 + k];
                    float4 v4 = *(const float4*)&Vs[k*68 + tx*4];
                    float bb[4] = {v4.x, v4.y, v4.z, v4.w};
                    #pragma unroll
                    for (int ii=0; ii<8; ii++)
                        #pragma unroll
                        for (int jj=0; jj<4; jj++) acc1[ii][jj] += a[ii]*bb[jj];
                }
                __syncthreads();
            }
        }
        {   // pass 2: Q_chunk(128x256) @ T_bd(256x64)
            float* Qs = St;           // [128][33]
            float* Ts = St + 128*33;  // [32][68]
            for (int e0 = 0; e0 < DIM; e0 += 32) {
                #pragma unroll
                for (int l = 0; l < 4; l++) {
                    int idx = tid + l*256;
                    int row = idx >> 3, c4 = (idx & 7)*4;
                    float4 q = *(const float4*)&g_Q[(size_t)(b*SEQ+c0+row)*DIM + e0 + c4];
                    Qs[row*33+c4+0]=q.x; Qs[row*33+c4+1]=q.y; Qs[row*33+c4+2]=q.z; Qs[row*33+c4+3]=q.w;
                }
                #pragma unroll
                for (int l = 0; l < 2; l++) {
                    int idx = tid + l*256;
                    int row = idx >> 4, c4 = (idx & 15)*4;
                    *(float4*)&Ts[row*68 + c4] =
                        *(const float4*)&g_T[((size_t)blk*DIM + e0 + row)*DIM + d0 + c4];
                }
                __syncthreads();
                #pragma unroll
                for (int e = 0; e < 32; e++) {
                    float a[8];
                    #pragma unroll
                    for (int ii=0; ii<8; ii++) a[ii] = Qs[(ty*8+ii)*33 + e];
                    float4 t4 = *(const float4*)&Ts[e*68 + tx*4];
                    float bb[4] = {t4.x, t4.y, t4.z, t4.w};
                    #pragma unroll
                    for (int ii=0; ii<8; ii++)
                        #pragma unroll
                        for (int jj=0; jj<4; jj++) acc2[ii][jj] += a[ii]*bb[jj];
                }
                __syncthreads();
            }
        }
        #pragma unroll
        for (int ii=0; ii<8; ii++) {
            int i = ty*8+ii;
            float rd = gpw[i]*GAMMA;   // gamma^{i+1}
            float4 o;
            o.x = acc1[ii][0] + rd*acc2[ii][0];
            o.y = acc1[ii][1] + rd*acc2[ii][1];
            o.z = acc1[ii][2] + rd*acc2[ii][2];
            o.w = acc1[ii][3] + rd*acc2[ii][3];
            *(float4*)&out[(size_t)(b*SEQ+c0+i)*DIM + d0 + tx*4] = o;
        }
    }
}

// -------------------------------------------------------------------------
extern "C" void kernel_launch(void* const* d_in, const int* in_sizes, int n_in,
                              void* d_out, int out_size) {
    const float* xq = (const float*)d_in[0];
    const float* xk = (const float*)d_in[1];
    const float* xv = (const float*)d_in[2];
    const float* Wq = (const float*)d_in[3];
    const float* bq = (const float*)d_in[4];
    const float* Wk = (const float*)d_in[5];
    const float* bk = (const float*)d_in[6];
    const float* Wv = (const float*)d_in[7];
    const float* bv = (const float*)d_in[8];
    float* out = (float*)d_out;

    cudaFuncSetAttribute(k_out, cudaFuncAttributeMaxDynamicSharedMemorySize, 104448);

    k_init  <<<16, 256>>>();
    k_proj  <<<dim3(BB*SEQ/64, DIM/64, 3), 256>>>(xq, xk, xv, Wq, bq, Wk, bk, Wv, bv);
    k_sloc  <<<BB*NCH, 256>>>();
    k_spref <<<BB, 256>>>();
    k_rdenom<<<BB*NCH, 256>>>();
    k_tloc  <<<dim3(BB*NCH, DIM/64, DIM/64), 256>>>();
    k_tpref <<<BB*DIM*DIM/256, 256>>>();
    k_out   <<<BB*NCH, 256, (128*133 + 128*33*2)*sizeof(float)>>>(out);
}

// round 3
// speedup vs baseline: 1.6447x; 1.6447x over previous
#include <cuda_runtime.h>
#include <cuda_bf16.h>
#include <math.h>
#include <stdint.h>

#define BB 4
#define SEQ 4096
#define DIM 256
#define CHK 128
#define NCH (SEQ/CHK)      // 32
#define GAMMA 0.9865f
#define INV16 0.0625f
#define ROWS_TOT (BB*SEQ)  // 16384

// ---------------- scratch (device globals; no allocation) ----------------
__device__ float g_Q[BB*SEQ*DIM];           // 16 MB
__device__ float g_K[BB*SEQ*DIM];           // 16 MB
__device__ float g_V[BB*SEQ*DIM];           // 16 MB
__device__ float g_ic[SEQ];                 // 1/sqrt(c_j)
__device__ float g_sloc[BB*NCH*DIM];
__device__ float g_sbd [BB*NCH*DIM];
__device__ float g_dinv[BB*SEQ];            // 1/denom
__device__ float g_T[(size_t)BB*NCH*DIM*DIM];   // 33.5 MB

// bf16 split operands for tensor-core projection
__device__ __nv_bfloat16 g_Xh[3*(size_t)ROWS_TOT*DIM];
__device__ __nv_bfloat16 g_Xl[3*(size_t)ROWS_TOT*DIM];
__device__ __nv_bfloat16 g_Wth[3*DIM*DIM];  // W^T, [n][k]
__device__ __nv_bfloat16 g_Wtl[3*DIM*DIM];

// ---------------- K0: column normalizer ic[j] = 1/sqrt(sum_k D[j,k]) -----
__global__ void k_init() {
    int j = blockIdx.x*256 + threadIdx.x;
    if (j < SEQ) {
        float lg = logf(GAMMA);
        float gp = expf((float)(j+1)*lg);
        g_ic[j] = rsqrtf((1.0f - gp)/(1.0f - GAMMA));
    }
}

// ---------------- convert inputs to bf16 hi/lo splits --------------------
__global__ void k_cvtX(const float* __restrict__ xq, const float* __restrict__ xk,
                       const float* __restrict__ xv) {
    int mat = blockIdx.y;
    const float* X = (mat==0) ? xq : (mat==1 ? xk : xv);
    size_t i = ((size_t)blockIdx.x*256 + threadIdx.x)*4;
    float4 v = *(const float4*)&X[i];
    __nv_bfloat16 h[4], l[4];
    float f[4] = {v.x, v.y, v.z, v.w};
    #pragma unroll
    for (int j = 0; j < 4; j++) {
        h[j] = __float2bfloat16(f[j]);
        l[j] = __float2bfloat16(f[j] - __bfloat162float(h[j]));
    }
    size_t o = (size_t)mat*ROWS_TOT*DIM + i;
    *(uint2*)&g_Xh[o] = *(uint2*)h;
    *(uint2*)&g_Xl[o] = *(uint2*)l;
}

__global__ void k_cvtW(const float* __restrict__ Wq, const float* __restrict__ Wk,
                       const float* __restrict__ Wv) {
    int mat = blockIdx.y;
    const float* W = (mat==0) ? Wq : (mat==1 ? Wk : Wv);
    int k = blockIdx.x, n = threadIdx.x;
    float w = W[k*DIM + n];
    __nv_bfloat16 h = __float2bfloat16(w);
    g_Wth[mat*DIM*DIM + n*DIM + k] = h;
    g_Wtl[mat*DIM*DIM + n*DIM + k] = __float2bfloat16(w - __bfloat162float(h));
}

// ---------------- warp mma.sync helper -----------------------------------
__device__ __forceinline__ void mma16816(float* c, const uint32_t* a, const uint32_t* b) {
    asm volatile(
        "mma.sync.aligned.m16n8k16.row.col.f32.bf16.bf16.f32 "
        "{%0,%1,%2,%3}, {%4,%5,%6,%7}, {%8,%9}, {%0,%1,%2,%3};"
        : "+f"(c[0]), "+f"(c[1]), "+f"(c[2]), "+f"(c[3])
        : "r"(a[0]), "r"(a[1]), "r"(a[2]), "r"(a[3]), "r"(b[0]), "r"(b[1]));
}

// ---------------- K1: projection via mma.sync (split-bf16, 3 passes) -----
// CTA: 128(M) x 128(N), K=256 in chunks of 32. 8 warps: 2(M) x 4(N),
// warp tile 64x32 = 4 m16-frags x 4 n8-frags.
#define PAD 40
__global__ void __launch_bounds__(256) k_proj_mma(
    const float* __restrict__ bq, const float* __restrict__ bk, const float* __restrict__ bv)
{
    __shared__ __nv_bfloat16 Ah[128*PAD];
    __shared__ __nv_bfloat16 Al[128*PAD];
    __shared__ __nv_bfloat16 Bh[128*PAD];
    __shared__ __nv_bfloat16 Bl[128*PAD];

    int tid = threadIdx.x;
    int warp = tid >> 5, lane = tid & 31;
    int wm = warp & 1, wn = warp >> 1;        // warp tile origin (wm*64, wn*32)
    int gr = lane >> 2, tg = lane & 3;

    int mat = blockIdx.z;
    int m0 = blockIdx.x * 128;
    int n0 = blockIdx.y * 128;

    const __nv_bfloat16* Xh = g_Xh + (size_t)mat*ROWS_TOT*DIM + (size_t)m0*DIM;
    const __nv_bfloat16* Xl = g_Xl + (size_t)mat*ROWS_TOT*DIM + (size_t)m0*DIM;
    const __nv_bfloat16* Wh = g_Wth + mat*DIM*DIM + (size_t)n0*DIM;
    const __nv_bfloat16* Wl = g_Wtl + mat*DIM*DIM + (size_t)n0*DIM;
    const float* bias = (mat==0) ? bq : (mat==1 ? bk : bv);
    float* O = ((mat==0) ? g_Q : (mat==1 ? g_K : g_V)) + (size_t)m0*DIM;

    float acc[4][4][4] = {};

    for (int k0 = 0; k0 < DIM; k0 += 32) {
        // stage 128x32 of each operand (uint4 = 8 bf16)
        #pragma unroll
        for (int l = 0; l < 2; l++) {
            int i = tid + l*256;              // 0..511
            int row = i >> 2, c8 = (i & 3)*8;
            *(uint4*)&Ah[row*PAD + c8] = *(const uint4*)&Xh[(size_t)row*DIM + k0 + c8];
            *(uint4*)&Al[row*PAD + c8] = *(const uint4*)&Xl[(size_t)row*DIM + k0 + c8];
            *(uint4*)&Bh[row*PAD + c8] = *(const uint4*)&Wh[(size_t)row*DIM + k0 + c8];
            *(uint4*)&Bl[row*PAD + c8] = *(const uint4*)&Wl[(size_t)row*DIM + k0 + c8];
        }
        __syncthreads();

        #pragma unroll
        for (int ks = 0; ks < 32; ks += 16) {
            uint32_t ah[4][4], al[4][4];
            int kc = ks + tg*2;
            #pragma unroll
            for (int mf = 0; mf < 4; mf++) {
                int r0 = wm*64 + mf*16 + gr;
                ah[mf][0] = *(const uint32_t*)&Ah[r0*PAD + kc];
                ah[mf][1] = *(const uint32_t*)&Ah[(r0+8)*PAD + kc];
                ah[mf][2] = *(const uint32_t*)&Ah[r0*PAD + kc + 8];
                ah[mf][3] = *(const uint32_t*)&Ah[(r0+8)*PAD + kc + 8];
                al[mf][0] = *(const uint32_t*)&Al[r0*PAD + kc];
                al[mf][1] = *(const uint32_t*)&Al[(r0+8)*PAD + kc];
                al[mf][2] = *(const uint32_t*)&Al[r0*PAD + kc + 8];
                al[mf][3] = *(const uint32_t*)&Al[(r0+8)*PAD + kc + 8];
            }
            #pragma unroll
            for (int nf = 0; nf < 4; nf++) {
                int n = wn*32 + nf*8 + gr;
                uint32_t bh[2], bl[2];
                bh[0] = *(const uint32_t*)&Bh[n*PAD + kc];
                bh[1] = *(const uint32_t*)&Bh[n*PAD + kc + 8];
                bl[0] = *(const uint32_t*)&Bl[n*PAD + kc];
                bl[1] = *(const uint32_t*)&Bl[n*PAD + kc + 8];
                #pragma unroll
                for (int mf = 0; mf < 4; mf++) {
                    mma16816(acc[mf][nf], ah[mf], bh);
                    mma16816(acc[mf][nf], ah[mf], bl);
                    mma16816(acc[mf][nf], al[mf], bh);
                }
            }
        }
        __syncthreads();
    }

    // epilogue: + bias, write float2 pairs
    #pragma unroll
    for (int nf = 0; nf < 4; nf++) {
        int col = n0 + wn*32 + nf*8 + tg*2;
        float b0 = bias[col], b1 = bias[col+1];
        #pragma unroll
        for (int mf = 0; mf < 4; mf++) {
            int row = wm*64 + mf*16 + gr;
            float2 o0, o1;
            o0.x = acc[mf][nf][0] + b0; o0.y = acc[mf][nf][1] + b1;
            o1.x = acc[mf][nf][2] + b0; o1.y = acc[mf][nf][3] + b1;
            *(float2*)&O[(size_t)row*DIM + col]     = o0;
            *(float2*)&O[(size_t)(row+8)*DIM + col] = o1;
        }
    }
}

// ---------------- K2: per-chunk local decayed K/sqrt(c) sum --------------
__global__ void k_sloc() {
    int blk = blockIdx.x; int b = blk/NCH; int c = blk%NCH; int c0 = c*CHK;
    int d = threadIdx.x;
    float s = 0.f;
    for (int j = 0; j < CHK; j++) {
        int gj = c0 + j;
        s = s*GAMMA + g_K[(size_t)(b*SEQ+gj)*DIM + d]*g_ic[gj];
    }
    g_sloc[blk*DIM + d] = s;
}

// ---------------- K3: prefix combine s across chunks ---------------------
__global__ void k_spref() {
    int b = blockIdx.x; int d = threadIdx.x;
    float gC = expf((float)CHK*logf(GAMMA));
    float s = 0.f;
    for (int c = 0; c < NCH; c++) {
        g_sbd[(b*NCH+c)*DIM + d] = s;
        s = s*gC + g_sloc[(b*NCH+c)*DIM + d];
    }
}

// ---------------- K4: r[b,j] = Q_j . S_j / 16 ;  denom_inv ---------------
__global__ void k_rdenom() {
    int blk = blockIdx.x; int b = blk/NCH; int c = blk%NCH; int c0 = c*CHK;
    int tid = threadIdx.x;
    int lane = tid & 31, wid = tid >> 5;
    __shared__ float red[8];
    float w = g_sbd[blk*DIM + tid];
    for (int j = 0; j < CHK; j++) {
        int gj = c0 + j;
        size_t p = (size_t)(b*SEQ + gj)*DIM + tid;
        w = w*GAMMA + g_K[p]*g_ic[gj];
        float pr = g_Q[p]*w;
        #pragma unroll
        for (int o = 16; o > 0; o >>= 1) pr += __shfl_xor_sync(0xffffffffu, pr, o);
        if (lane == 0) red[wid] = pr;
        __syncthreads();
        if (tid == 0) {
            float r = 0.f;
            #pragma unroll
            for (int k = 0; k < 8; k++) r += red[k];
            r *= INV16;
            g_dinv[b*SEQ + gj] = 1.0f / fmaxf(fabsf(r), 1.0f);
        }
        __syncthreads();
    }
}

// ---------------- K5: chunk-local T = sum_j w_j Khat_j V_j^T -------------
__global__ void __launch_bounds__(256) k_tloc() {
    __shared__ float Ks[32*64];
    __shared__ float Vs[32*64];
    __shared__ float gpw[CHK];
    int blk = blockIdx.x; int b = blk/NCH; int c = blk%NCH; int c0 = c*CHK;
    int tid = threadIdx.x;
    if (tid < CHK) gpw[tid] = expf((float)tid * logf(GAMMA));
    __syncthreads();
    int tx = tid & 15, ty = tid >> 4;
    int d1t = blockIdx.y * 64, d2t = blockIdx.z * 64;
    float acc[4][4] = {};
    for (int j0 = 0; j0 < CHK; j0 += 32) {
        #pragma unroll
        for (int l = 0; l < 2; l++) {
            int idx = tid + l*256;
            int row = idx >> 4, c4 = (idx & 15)*4;
            int gj = c0 + j0 + row;
            float w = gpw[CHK-1-(j0+row)] * g_ic[gj] * INV16 * g_dinv[b*SEQ + gj];
            float4 kv = *(const float4*)&g_K[(size_t)(b*SEQ+gj)*DIM + d1t + c4];
            kv.x*=w; kv.y*=w; kv.z*=w; kv.w*=w;
            *(float4*)&Ks[row*64 + c4] = kv;
            *(float4*)&Vs[row*64 + c4] = *(const float4*)&g_V[(size_t)(b*SEQ+gj)*DIM + d2t + c4];
        }
        __syncthreads();
        #pragma unroll
        for (int j = 0; j < 32; j++) {
            float a[4];
            #pragma unroll
            for (int ii=0; ii<4; ii++) a[ii] = Ks[j*64 + ty*4 + ii];
            float4 v4 = *(const float4*)&Vs[j*64 + tx*4];
            float bb[4] = {v4.x, v4.y, v4.z, v4.w};
            #pragma unroll
            for (int ii=0; ii<4; ii++)
                #pragma unroll
                for (int jj=0; jj<4; jj++) acc[ii][jj] += a[ii]*bb[jj];
        }
        __syncthreads();
    }
    #pragma unroll
    for (int ii=0; ii<4; ii++) {
        int d1 = d1t + ty*4 + ii;
        float4 o; o.x=acc[ii][0]; o.y=acc[ii][1]; o.z=acc[ii][2]; o.w=acc[ii][3];
        *(float4*)&g_T[((size_t)blk*DIM + d1)*DIM + d2t + tx*4] = o;
    }
}

// ---------------- K6: in-place prefix of T over chunks -------------------
__global__ void k_tpref() {
    int idx = blockIdx.x*256 + threadIdx.x;
    int b   = idx >> 16;
    int off = idx & 65535;
    float gC = expf((float)CHK * logf(GAMMA));
    float t = 0.f;
    for (int c = 0; c < NCH; c++) {
        size_t p = (((size_t)(b*NCH + c)) << 16) + off;
        float lc = g_T[p];
        g_T[p] = t;
        t = t*gC + lc;
    }
}

// ---------------- K7: fused output per chunk -----------------------------
__global__ void __launch_bounds__(256) k_out(float* __restrict__ out) {
    extern __shared__ float smf[];
    float* Asm = smf;                // [128][133]
    float* St  = smf + 128*133;
    __shared__ float gpw[CHK];
    __shared__ float colw[CHK];
    int blk = blockIdx.x; int b = blk/NCH; int c = blk%NCH; int c0 = c*CHK;
    int tid = threadIdx.x; int tx = tid & 15, ty = tid >> 4;
    if (tid < CHK) {
        gpw[tid] = expf((float)tid * logf(GAMMA));
        int gj = c0 + tid;
        colw[tid] = g_ic[gj]*INV16*g_dinv[b*SEQ + gj];
    }
    __syncthreads();

    {   // Phase A: A = Q_chunk @ K_chunk^T
        float acc[8][8] = {};
        float* Qs = St;
        float* Ks = St + 128*33;
        for (int e0 = 0; e0 < DIM; e0 += 32) {
            #pragma unroll
            for (int l = 0; l < 4; l++) {
                int idx = tid + l*256;
                int row = idx >> 3, c4 = (idx & 7)*4;
                size_t p = (size_t)(b*SEQ+c0+row)*DIM + e0 + c4;
                float4 q = *(const float4*)&g_Q[p];
                Qs[row*33+c4+0]=q.x; Qs[row*33+c4+1]=q.y; Qs[row*33+c4+2]=q.z; Qs[row*33+c4+3]=q.w;
                float4 k4 = *(const float4*)&g_K[p];
                Ks[row*33+c4+0]=k4.x; Ks[row*33+c4+1]=k4.y; Ks[row*33+c4+2]=k4.z; Ks[row*33+c4+3]=k4.w;
            }
            __syncthreads();
            #pragma unroll
            for (int e = 0; e < 32; e++) {
                float a[8], bb[8];
                #pragma unroll
                for (int ii=0; ii<8; ii++) a[ii]  = Qs[(ty*8+ii)*33 + e];
                #pragma unroll
                for (int kk=0; kk<8; kk++) bb[kk] = Ks[(tx*8+kk)*33 + e];
                #pragma unroll
                for (int ii=0; ii<8; ii++)
                    #pragma unroll
                    for (int kk=0; kk<8; kk++) acc[ii][kk] += a[ii]*bb[kk];
            }
            __syncthreads();
        }
        #pragma unroll
        for (int ii=0; ii<8; ii++) {
            int i = ty*8+ii;
            #pragma unroll
            for (int kk=0; kk<8; kk++) {
                int k = tx*8+kk;
                float v = (i >= k) ? acc[ii][kk]*gpw[i-k]*colw[k] : 0.0f;
                Asm[i*133 + k] = v;
            }
        }
        __syncthreads();
    }

    for (int d0 = 0; d0 < DIM; d0 += 64) {
        float acc1[8][4] = {};
        float acc2[8][4] = {};
        {   // pass 1: Asm(128x128) @ V_chunk(128x64)
            float* Vs = St;
            for (int k0 = 0; k0 < CHK; k0 += 32) {
                #pragma unroll
                for (int l = 0; l < 2; l++) {
                    int idx = tid + l*256;
                    int row = idx >> 4, c4 = (idx & 15)*4;
                    *(float4*)&Vs[row*68 + c4] =
                        *(const float4*)&g_V[(size_t)(b*SEQ+c0+k0+row)*DIM + d0 + c4];
                }
                __syncthreads();
                #pragma unroll
                for (int k = 0; k < 32; k++) {
                    float a[8];
                    #pragma unroll
                    for (int ii=0; ii<8; ii++) a[ii] = Asm[(ty*8+ii)*133 + k0 + k];
                    float4 v4 = *(const float4*)&Vs[k*68 + tx*4];
                    float bb[4] = {v4.x, v4.y, v4.z, v4.w};
                    #pragma unroll
                    for (int ii=0; ii<8; ii++)
                        #pragma unroll
                        for (int jj=0; jj<4; jj++) acc1[ii][jj] += a[ii]*bb[jj];
                }
                __syncthreads();
            }
        }
        {   // pass 2: Q_chunk(128x256) @ T_bd(256x64)
            float* Qs = St;
            float* Ts = St + 128*33;
            for (int e0 = 0; e0 < DIM; e0 += 32) {
                #pragma unroll
                for (int l = 0; l < 4; l++) {
                    int idx = tid + l*256;
                    int row = idx >> 3, c4 = (idx & 7)*4;
                    float4 q = *(const float4*)&g_Q[(size_t)(b*SEQ+c0+row)*DIM + e0 + c4];
                    Qs[row*33+c4+0]=q.x; Qs[row*33+c4+1]=q.y; Qs[row*33+c4+2]=q.z; Qs[row*33+c4+3]=q.w;
                }
                #pragma unroll
                for (int l = 0; l < 2; l++) {
                    int idx = tid + l*256;
                    int row = idx >> 4, c4 = (idx & 15)*4;
                    *(float4*)&Ts[row*68 + c4] =
                        *(const float4*)&g_T[((size_t)blk*DIM + e0 + row)*DIM + d0 + c4];
                }
                __syncthreads();
                #pragma unroll
                for (int e = 0; e < 32; e++) {
                    float a[8];
                    #pragma unroll
                    for (int ii=0; ii<8; ii++) a[ii] = Qs[(ty*8+ii)*33 + e];
                    float4 t4 = *(const float4*)&Ts[e*68 + tx*4];
                    float bb[4] = {t4.x, t4.y, t4.z, t4.w};
                    #pragma unroll
                    for (int ii=0; ii<8; ii++)
                        #pragma unroll
                        for (int jj=0; jj<4; jj++) acc2[ii][jj] += a[ii]*bb[jj];
                }
                __syncthreads();
            }
        }
        #pragma unroll
        for (int ii=0; ii<8; ii++) {
            int i = ty*8+ii;
            float rd = gpw[i]*GAMMA;
            float4 o;
            o.x = acc1[ii][0] + rd*acc2[ii][0];
            o.y = acc1[ii][1] + rd*acc2[ii][1];
            o.z = acc1[ii][2] + rd*acc2[ii][2];
            o.w = acc1[ii][3] + rd*acc2[ii][3];
            *(float4*)&out[(size_t)(b*SEQ+c0+i)*DIM + d0 + tx*4] = o;
        }
    }
}

// -------------------------------------------------------------------------
extern "C" void kernel_launch(void* const* d_in, const int* in_sizes, int n_in,
                              void* d_out, int out_size) {
    const float* xq = (const float*)d_in[0];
    const float* xk = (const float*)d_in[1];
    const float* xv = (const float*)d_in[2];
    const float* Wq = (const float*)d_in[3];
    const float* bq = (const float*)d_in[4];
    const float* Wk = (const float*)d_in[5];
    const float* bk = (const float*)d_in[6];
    const float* Wv = (const float*)d_in[7];
    const float* bv = (const float*)d_in[8];
    float* out = (float*)d_out;

    static int once = 0;
    if (!once) {
        cudaFuncSetAttribute(k_out, cudaFuncAttributeMaxDynamicSharedMemorySize, 104448);
        once = 1;
    }

    k_init  <<<16, 256>>>();
    k_cvtW  <<<dim3(DIM, 3), 256>>>(Wq, Wk, Wv);
    k_cvtX  <<<dim3(ROWS_TOT*DIM/4/256, 3), 256>>>(xq, xk, xv);
    k_proj_mma<<<dim3(ROWS_TOT/128, DIM/128, 3), 256>>>(bq, bk, bv);
    k_sloc  <<<BB*NCH, 256>>>();
    k_spref <<<BB, 256>>>();
    k_rdenom<<<BB*NCH, 256>>>();
    k_tloc  <<<dim3(BB*NCH, DIM/64, DIM/64), 256>>>();
    k_tpref <<<BB*DIM*DIM/256, 256>>>();
    k_out   <<<BB*NCH, 256, (128*133 + 128*33*2)*sizeof(float)>>>(out);
}

// round 4
// speedup vs baseline: 2.1620x; 1.3146x over previous
#include <cuda_runtime.h>
#include <cuda_bf16.h>
#include <math.h>
#include <stdint.h>

#define BB 4
#define SEQ 4096
#define DIM 256
#define CHK 128
#define NCH (SEQ/CHK)      // 32
#define GAMMA 0.9865f
#define INV16 0.0625f
#define ROWS_TOT (BB*SEQ)  // 16384

// ---------------- scratch (device globals; no allocation) ----------------
__device__ float g_Q[BB*SEQ*DIM];           // fp32 Q (scans + B2 restage)
__device__ float g_K[BB*SEQ*DIM];           // fp32 K (scans + tloc restage)
__device__ float g_ic[SEQ];
__device__ float g_sloc[BB*NCH*DIM];
__device__ float g_sbd [BB*NCH*DIM];
__device__ float g_dinv[BB*SEQ];
__device__ float g_T[(size_t)BB*NCH*DIM*DIM];        // chunk-local T (fp32)
__device__ __nv_bfloat16 g_Th[(size_t)BB*NCH*DIM*DIM]; // prefix T hi
__device__ __nv_bfloat16 g_Tl[(size_t)BB*NCH*DIM*DIM]; // prefix T lo

// bf16 hi/lo splits of Q,K,V (written by proj epilogue)
__device__ __nv_bfloat16 g_Qh[BB*SEQ*DIM];
__device__ __nv_bfloat16 g_Ql[BB*SEQ*DIM];
__device__ __nv_bfloat16 g_Kh[BB*SEQ*DIM];
__device__ __nv_bfloat16 g_Kl[BB*SEQ*DIM];
__device__ __nv_bfloat16 g_Vh[BB*SEQ*DIM];
__device__ __nv_bfloat16 g_Vl[BB*SEQ*DIM];

// bf16 splits of W^T ([n][k])
__device__ __nv_bfloat16 g_Wth[3*DIM*DIM];
__device__ __nv_bfloat16 g_Wtl[3*DIM*DIM];

// ======================= helpers =========================================
__device__ __forceinline__ uint32_t smem_u32(const void* p) {
    uint32_t a;
    asm("{ .reg .u64 t; cvta.to.shared.u64 t, %1; cvt.u32.u64 %0, t; }" : "=r"(a) : "l"(p));
    return a;
}
__device__ __forceinline__ void mma16816(float* c, const uint32_t* a, const uint32_t* b) {
    asm volatile(
        "mma.sync.aligned.m16n8k16.row.col.f32.bf16.bf16.f32 "
        "{%0,%1,%2,%3}, {%4,%5,%6,%7}, {%8,%9}, {%0,%1,%2,%3};"
        : "+f"(c[0]), "+f"(c[1]), "+f"(c[2]), "+f"(c[3])
        : "r"(a[0]), "r"(a[1]), "r"(a[2]), "r"(a[3]), "r"(b[0]), "r"(b[1]));
}
__device__ __forceinline__ void ldsm4t(uint32_t* r, uint32_t a) {
    asm volatile("ldmatrix.sync.aligned.m8n8.x4.trans.shared.b16 {%0,%1,%2,%3}, [%4];"
        : "=r"(r[0]), "=r"(r[1]), "=r"(r[2]), "=r"(r[3]) : "r"(a));
}
// direct A-frag load from row-major [m][k] bf16 buffer (elem leading dim L)
__device__ __forceinline__ void lda_dir(uint32_t* a, const char* base, int row, int kc, int L) {
    a[0] = *(const uint32_t*)(base + (row*L + kc)*2);
    a[1] = *(const uint32_t*)(base + ((row+8)*L + kc)*2);
    a[2] = *(const uint32_t*)(base + (row*L + kc + 8)*2);
    a[3] = *(const uint32_t*)(base + ((row+8)*L + kc + 8)*2);
}
// ldmatrix.trans address for B-frag tile (k16 x n16) from [k rows][n cols] buffer
__device__ __forceinline__ uint32_t baddr(uint32_t base, int lane, int k0, int n0, int L) {
    int row = k0 + (lane & 7) + ((lane >> 3) & 1)*8;
    int col = n0 + ((lane >> 4) & 1)*8;
    return base + (uint32_t)(row*L + col)*2;
}
// ldmatrix.trans address for A-frag tile (m16 x k16) from [k rows][m cols] buffer
__device__ __forceinline__ uint32_t aaddr_t(uint32_t base, int lane, int m0, int k0, int L) {
    int row = k0 + (lane & 7) + ((lane >> 4) & 1)*8;
    int col = m0 + ((lane >> 3) & 1)*8;
    return base + (uint32_t)(row*L + col)*2;
}
// split two floats into bf16 hi (returned) / lo (out param), packed words
__device__ __forceinline__ uint32_t pack2(float a, float b, uint32_t& lo) {
    __nv_bfloat16 ha = __float2bfloat16(a), hb = __float2bfloat16(b);
    __nv_bfloat162 hh; hh.x = ha; hh.y = hb;
    __nv_bfloat162 ll;
    ll.x = __float2bfloat16(a - __bfloat162float(ha));
    ll.y = __float2bfloat16(b - __bfloat162float(hb));
    lo = *(uint32_t*)&ll;
    return *(uint32_t*)&hh;
}

// ---------------- K0 -----------------------------------------------------
__global__ void k_init() {
    int j = blockIdx.x*256 + threadIdx.x;
    if (j < SEQ) {
        float lg = logf(GAMMA);
        float gp = expf((float)(j+1)*lg);
        g_ic[j] = rsqrtf((1.0f - gp)/(1.0f - GAMMA));
    }
}

__global__ void k_cvtW(const float* __restrict__ Wq, const float* __restrict__ Wk,
                       const float* __restrict__ Wv) {
    int mat = blockIdx.y;
    const float* W = (mat==0) ? Wq : (mat==1 ? Wk : Wv);
    int k = blockIdx.x, n = threadIdx.x;
    float w = W[k*DIM + n];
    __nv_bfloat16 h = __float2bfloat16(w);
    g_Wth[mat*DIM*DIM + n*DIM + k] = h;
    g_Wtl[mat*DIM*DIM + n*DIM + k] = __float2bfloat16(w - __bfloat162float(h));
}

// ---------------- K1: projection (inline X split, split epilogue) --------
#define PAD 40
__global__ void __launch_bounds__(256) k_proj_mma(
    const float* __restrict__ xq, const float* __restrict__ xk, const float* __restrict__ xv,
    const float* __restrict__ bq, const float* __restrict__ bk, const float* __restrict__ bv)
{
    __shared__ __nv_bfloat16 Ah[128*PAD];
    __shared__ __nv_bfloat16 Al[128*PAD];
    __shared__ __nv_bfloat16 Bh[128*PAD];
    __shared__ __nv_bfloat16 Bl[128*PAD];

    int tid = threadIdx.x;
    int warp = tid >> 5, lane = tid & 31;
    int wm = warp & 1, wn = warp >> 1;
    int gr = lane >> 2, tg = lane & 3;

    int mat = blockIdx.z;
    int m0 = blockIdx.x * 128;
    int n0 = blockIdx.y * 128;

    const float* X = (mat==0) ? xq : (mat==1 ? xk : xv);
    X += (size_t)m0*DIM;
    const __nv_bfloat16* Wh = g_Wth + mat*DIM*DIM + (size_t)n0*DIM;
    const __nv_bfloat16* Wl = g_Wtl + mat*DIM*DIM + (size_t)n0*DIM;
    const float* bias = (mat==0) ? bq : (mat==1 ? bk : bv);
    float* O = ((mat==0) ? g_Q : g_K) + (size_t)m0*DIM;     // fp32 only for Q,K
    __nv_bfloat16* OH = ((mat==0) ? g_Qh : (mat==1 ? g_Kh : g_Vh)) + (size_t)m0*DIM;
    __nv_bfloat16* OL = ((mat==0) ? g_Ql : (mat==1 ? g_Kl : g_Vl)) + (size_t)m0*DIM;

    float acc[4][4][4] = {};

    for (int k0 = 0; k0 < DIM; k0 += 32) {
        // X: 128x32 fp32 -> split into Ah/Al
        #pragma unroll
        for (int l = 0; l < 4; l++) {
            int i = tid + l*256;              // 1024 float4 units
            int row = i >> 3, c4 = (i & 7)*4;
            float4 v = *(const float4*)&X[(size_t)row*DIM + k0 + c4];
            uint32_t l01, l23;
            uint32_t h01 = pack2(v.x, v.y, l01);
            uint32_t h23 = pack2(v.z, v.w, l23);
            *(uint2*)&Ah[row*PAD + c4] = make_uint2(h01, h23);
            *(uint2*)&Al[row*PAD + c4] = make_uint2(l01, l23);
        }
        // W: copy bf16
        #pragma unroll
        for (int l = 0; l < 2; l++) {
            int i = tid + l*256;              // 512 uint4 units
            int row = i >> 2, c8 = (i & 3)*8;
            *(uint4*)&Bh[row*PAD + c8] = *(const uint4*)&Wh[(size_t)row*DIM + k0 + c8];
            *(uint4*)&Bl[row*PAD + c8] = *(const uint4*)&Wl[(size_t)row*DIM + k0 + c8];
        }
        __syncthreads();

        #pragma unroll
        for (int ks = 0; ks < 32; ks += 16) {
            uint32_t ah[4][4], al[4][4];
            int kc = ks + tg*2;
            #pragma unroll
            for (int mf = 0; mf < 4; mf++) {
                int r0 = wm*64 + mf*16 + gr;
                ah[mf][0] = *(const uint32_t*)&Ah[r0*PAD + kc];
                ah[mf][1] = *(const uint32_t*)&Ah[(r0+8)*PAD + kc];
                ah[mf][2] = *(const uint32_t*)&Ah[r0*PAD + kc + 8];
                ah[mf][3] = *(const uint32_t*)&Ah[(r0+8)*PAD + kc + 8];
                al[mf][0] = *(const uint32_t*)&Al[r0*PAD + kc];
                al[mf][1] = *(const uint32_t*)&Al[(r0+8)*PAD + kc];
                al[mf][2] = *(const uint32_t*)&Al[r0*PAD + kc + 8];
                al[mf][3] = *(const uint32_t*)&Al[(r0+8)*PAD + kc + 8];
            }
            #pragma unroll
            for (int nf = 0; nf < 4; nf++) {
                int n = wn*32 + nf*8 + gr;
                uint32_t bh[2], bl[2];
                bh[0] = *(const uint32_t*)&Bh[n*PAD + kc];
                bh[1] = *(const uint32_t*)&Bh[n*PAD + kc + 8];
                bl[0] = *(const uint32_t*)&Bl[n*PAD + kc];
                bl[1] = *(const uint32_t*)&Bl[n*PAD + kc + 8];
                #pragma unroll
                for (int mf = 0; mf < 4; mf++) {
                    mma16816(acc[mf][nf], ah[mf], bh);
                    mma16816(acc[mf][nf], ah[mf], bl);
                    mma16816(acc[mf][nf], al[mf], bh);
                }
            }
        }
        __syncthreads();
    }

    // epilogue: +bias; fp32 (Q,K) and bf16 hi/lo (all)
    #pragma unroll
    for (int nf = 0; nf < 4; nf++) {
        int col = n0 + wn*32 + nf*8 + tg*2;
        float b0 = bias[col], b1 = bias[col+1];
        #pragma unroll
        for (int mf = 0; mf < 4; mf++) {
            int row = wm*64 + mf*16 + gr;
            float2 o0, o1;
            o0.x = acc[mf][nf][0] + b0; o0.y = acc[mf][nf][1] + b1;
            o1.x = acc[mf][nf][2] + b0; o1.y = acc[mf][nf][3] + b1;
            uint32_t lw0, lw1;
            uint32_t hw0 = pack2(o0.x, o0.y, lw0);
            uint32_t hw1 = pack2(o1.x, o1.y, lw1);
            *(uint32_t*)&OH[(size_t)row*DIM + col]     = hw0;
            *(uint32_t*)&OL[(size_t)row*DIM + col]     = lw0;
            *(uint32_t*)&OH[(size_t)(row+8)*DIM + col] = hw1;
            *(uint32_t*)&OL[(size_t)(row+8)*DIM + col] = lw1;
            if (mat < 2) {
                *(float2*)&O[(size_t)row*DIM + col]     = o0;
                *(float2*)&O[(size_t)(row+8)*DIM + col] = o1;
            }
        }
    }
}

// ---------------- K2: per-chunk local decayed K/sqrt(c) sum --------------
__global__ void k_sloc() {
    int blk = blockIdx.x; int b = blk/NCH; int c = blk%NCH; int c0 = c*CHK;
    int d = threadIdx.x;
    float s = 0.f;
    for (int j = 0; j < CHK; j++) {
        int gj = c0 + j;
        s = s*GAMMA + g_K[(size_t)(b*SEQ+gj)*DIM + d]*g_ic[gj];
    }
    g_sloc[blk*DIM + d] = s;
}

// ---------------- K3: prefix (prefetch all chunks into regs) -------------
__global__ void k_spref() {
    int b = blockIdx.x; int d = threadIdx.x;
    float v[NCH];
    #pragma unroll
    for (int c = 0; c < NCH; c++) v[c] = g_sloc[(b*NCH+c)*DIM + d];
    float gC = __expf(128.f*logf(GAMMA));
    float s = 0.f;
    #pragma unroll
    for (int c = 0; c < NCH; c++) { g_sbd[(b*NCH+c)*DIM + d] = s; s = s*gC + v[c]; }
}

// ---------------- K4: denom via single-warp scan --------------------------
__global__ void k_rdenom() {   // grid BB*NCH, 32 threads
    int blk = blockIdx.x, b = blk >> 5, c = blk & 31, c0 = c*CHK;
    int lane = threadIdx.x;
    int d0 = lane*8;
    float w[8];
    *(float4*)&w[0] = *(const float4*)&g_sbd[blk*DIM + d0];
    *(float4*)&w[4] = *(const float4*)&g_sbd[blk*DIM + d0 + 4];
    for (int j = 0; j < CHK; j++) {
        int gj = c0 + j;
        size_t p = (size_t)(b*SEQ+gj)*DIM + d0;
        float ic = g_ic[gj];
        float4 k1 = *(const float4*)&g_K[p], k2 = *(const float4*)&g_K[p+4];
        float4 q1 = *(const float4*)&g_Q[p], q2 = *(const float4*)&g_Q[p+4];
        w[0] = w[0]*GAMMA + k1.x*ic;  w[1] = w[1]*GAMMA + k1.y*ic;
        w[2] = w[2]*GAMMA + k1.z*ic;  w[3] = w[3]*GAMMA + k1.w*ic;
        w[4] = w[4]*GAMMA + k2.x*ic;  w[5] = w[5]*GAMMA + k2.y*ic;
        w[6] = w[6]*GAMMA + k2.z*ic;  w[7] = w[7]*GAMMA + k2.w*ic;
        float pr = q1.x*w[0] + q1.y*w[1] + q1.z*w[2] + q1.w*w[3]
                 + q2.x*w[4] + q2.y*w[5] + q2.z*w[6] + q2.w*w[7];
        #pragma unroll
        for (int o = 16; o > 0; o >>= 1) pr += __shfl_xor_sync(0xffffffffu, pr, o);
        if (lane == 0) g_dinv[b*SEQ + gj] = 1.0f / fmaxf(fabsf(pr*INV16), 1.0f);
    }
}

// ---------------- K5: chunk-local T via MMA (both operands ldsm.trans) ---
#define TL_KH 0
#define TL_KL 34816
#define TL_VH 69632
#define TL_VL 104448
#define SM_TLOC 139264
__global__ void __launch_bounds__(256) k_tloc() {
    extern __shared__ char sm[];
    __shared__ float w2[128];
    int tid = threadIdx.x;
    int lane = tid & 31, warp = tid >> 5;
    int gr = lane >> 2, tg = lane & 3;
    int wm = warp >> 1, wn = warp & 1;
    int blk = blockIdx.x, b = blk >> 5, c = blk & 31, c0 = c*CHK;
    int d1t = blockIdx.y*128, d2t = blockIdx.z*128;

    if (tid < 128) {
        int gj = c0 + tid;
        w2[tid] = __expf((float)(127-tid)*logf(GAMMA)) * g_ic[gj]*INV16*g_dinv[b*SEQ+gj];
    }
    __syncthreads();

    // stage wK = w_j * K (re-split from fp32) as [j][d1] bf16 hi/lo
    #pragma unroll
    for (int l = 0; l < 16; l++) {
        int u = tid + l*256;
        int row = u >> 5, c4 = (u & 31)*4;
        float w = w2[row];
        float4 kv = *(const float4*)&g_K[(size_t)(b*SEQ+c0+row)*DIM + d1t + c4];
        uint32_t l01, l23;
        uint32_t h01 = pack2(kv.x*w, kv.y*w, l01);
        uint32_t h23 = pack2(kv.z*w, kv.w*w, l23);
        *(uint2*)(sm + TL_KH + (row*136 + c4)*2) = make_uint2(h01, h23);
        *(uint2*)(sm + TL_KL + (row*136 + c4)*2) = make_uint2(l01, l23);
    }
    // stage V hi/lo copy [j][d2]
    #pragma unroll
    for (int l = 0; l < 8; l++) {
        int u = tid + l*256;
        int row = u >> 4, c8 = (u & 15)*8;
        size_t gp = (size_t)(b*SEQ+c0+row)*DIM + d2t + c8;
        *(uint4*)(sm + TL_VH + (row*136 + c8)*2) = *(const uint4*)&g_Vh[gp];
        *(uint4*)(sm + TL_VL + (row*136 + c8)*2) = *(const uint4*)&g_Vl[gp];
    }
    __syncthreads();

    uint32_t smb = smem_u32(sm);
    float acc[2][8][4] = {};
    for (int ks = 0; ks < 128; ks += 16) {
        uint32_t ah[2][4], al[2][4];
        #pragma unroll
        for (int mf = 0; mf < 2; mf++) {
            ldsm4t(ah[mf], aaddr_t(smb + TL_KH, lane, wm*32 + mf*16, ks, 136));
            ldsm4t(al[mf], aaddr_t(smb + TL_KL, lane, wm*32 + mf*16, ks, 136));
        }
        #pragma unroll
        for (int nfp = 0; nfp < 4; nfp++) {
            uint32_t bh[4], bl[4];
            ldsm4t(bh, baddr(smb + TL_VH, lane, ks, wn*64 + nfp*16, 136));
            ldsm4t(bl, baddr(smb + TL_VL, lane, ks, wn*64 + nfp*16, 136));
            #pragma unroll
            for (int mf = 0; mf < 2; mf++) {
                mma16816(acc[mf][2*nfp],   ah[mf], bh);
                mma16816(acc[mf][2*nfp+1], ah[mf], bh+2);
                mma16816(acc[mf][2*nfp],   ah[mf], bl);
                mma16816(acc[mf][2*nfp+1], ah[mf], bl+2);
                mma16816(acc[mf][2*nfp],   al[mf], bh);
                mma16816(acc[mf][2*nfp+1], al[mf], bh+2);
            }
        }
    }
    #pragma unroll
    for (int mf = 0; mf < 2; mf++) {
        int d1 = d1t + wm*32 + mf*16 + gr;
        #pragma unroll
        for (int nf = 0; nf < 8; nf++) {
            int d2 = d2t + wn*64 + nf*8 + tg*2;
            *(float2*)&g_T[((size_t)blk*DIM + d1)*DIM + d2]     = make_float2(acc[mf][nf][0], acc[mf][nf][1]);
            *(float2*)&g_T[((size_t)blk*DIM + d1 + 8)*DIM + d2] = make_float2(acc[mf][nf][2], acc[mf][nf][3]);
        }
    }
}

// ---------------- K6: prefix of T over chunks -> bf16 hi/lo ---------------
__global__ void k_tpref() {
    int idx = blockIdx.x*256 + threadIdx.x;
    int b   = idx >> 16;
    int off = idx & 65535;
    float gC = __expf(128.f*logf(GAMMA));
    float t = 0.f;
    for (int c = 0; c < NCH; c++) {
        size_t p = (((size_t)(b*NCH + c)) << 16) + off;
        float lc = g_T[p];
        __nv_bfloat16 h = __float2bfloat16(t);
        g_Th[p] = h;
        g_Tl[p] = __float2bfloat16(t - __bfloat162float(h));
        t = t*gC + lc;
    }
}

// ---------------- K7: fused output, 3 MMA phases --------------------------
#define SO_SH 0
#define SO_SL 34816
#define SO_R1 69632
#define SA_QH (SO_R1 + 0)
#define SA_QL (SO_R1 + 18432)
#define SA_KH (SO_R1 + 36864)
#define SA_KL (SO_R1 + 55296)
#define SB_VH (SO_R1 + 0)
#define SB_VL (SO_R1 + 34816)
#define SB_QH (SO_R1 + 0)
#define SB_QL (SO_R1 + 18432)
#define SB_TH (SO_R1 + 36864)
#define SB_TL (SO_R1 + 54272)
#define SM_KOUT 143360
__global__ void __launch_bounds__(256) k_out(float* __restrict__ out) {
    extern __shared__ char sm[];
    __shared__ float rowg[128];
    __shared__ float cw2[128];
    int tid = threadIdx.x;
    int lane = tid & 31, warp = tid >> 5;
    int gr = lane >> 2, tg = lane & 3;
    int wm = warp >> 1, wn = warp & 1;
    int blk = blockIdx.x, b = blk >> 5, c = blk & 31, c0 = c*CHK;

    if (tid < 128) {
        float gi = __expf((float)tid * logf(GAMMA));
        rowg[tid] = gi;
        int gj = c0 + tid;
        cw2[tid] = g_ic[gj]*INV16*g_dinv[b*SEQ+gj] / gi;
    }
    __syncthreads();
    uint32_t smb = smem_u32(sm);

    // ======== Phase A: S = Q K^T (128x128, K=256), direct frag loads ====
    float accA[2][8][4] = {};
    for (int e0 = 0; e0 < DIM; e0 += 64) {
        #pragma unroll
        for (int l = 0; l < 4; l++) {
            int u = tid + l*256;              // 128 rows x 8 uint4
            int row = u >> 3, c8 = (u & 7)*8;
            size_t gp = (size_t)(b*SEQ + c0 + row)*DIM + e0 + c8;
            *(uint4*)(sm + SA_QH + (row*72 + c8)*2) = *(const uint4*)&g_Qh[gp];
            *(uint4*)(sm + SA_QL + (row*72 + c8)*2) = *(const uint4*)&g_Ql[gp];
            *(uint4*)(sm + SA_KH + (row*72 + c8)*2) = *(const uint4*)&g_Kh[gp];
            *(uint4*)(sm + SA_KL + (row*72 + c8)*2) = *(const uint4*)&g_Kl[gp];
        }
        __syncthreads();
        for (int ks = 0; ks < 64; ks += 16) {
            int kc = ks + tg*2;
            uint32_t ah[2][4], al[2][4];
            #pragma unroll
            for (int mf = 0; mf < 2; mf++) {
                int r = wm*32 + mf*16 + gr;
                lda_dir(ah[mf], sm + SA_QH, r, kc, 72);
                lda_dir(al[mf], sm + SA_QL, r, kc, 72);
            }
            #pragma unroll
            for (int nf = 0; nf < 8; nf++) {
                int n = wn*64 + nf*8 + gr;
                uint32_t bh[2], bl[2];
                bh[0] = *(const uint32_t*)(sm + SA_KH + (n*72 + kc)*2);
                bh[1] = *(const uint32_t*)(sm + SA_KH + (n*72 + kc + 8)*2);
                bl[0] = *(const uint32_t*)(sm + SA_KL + (n*72 + kc)*2);
                bl[1] = *(const uint32_t*)(sm + SA_KL + (n*72 + kc + 8)*2);
                #pragma unroll
                for (int mf = 0; mf < 2; mf++) {
                    mma16816(accA[mf][nf], ah[mf], bh);
                    mma16816(accA[mf][nf], ah[mf], bl);
                    mma16816(accA[mf][nf], al[mf], bh);
                }
            }
        }
        __syncthreads();
    }
    // mask + decay weights, split into Ssm hi/lo
    #pragma unroll
    for (int mf = 0; mf < 2; mf++) {
        int i1 = wm*32 + mf*16 + gr, i2 = i1 + 8;
        float r1 = rowg[i1], r2 = rowg[i2];
        #pragma unroll
        for (int nf = 0; nf < 8; nf++) {
            int j = wn*64 + nf*8 + tg*2;
            float cj0 = cw2[j], cj1 = cw2[j+1];
            float v0 = (i1 >= j)   ? accA[mf][nf][0]*r1*cj0 : 0.f;
            float v1 = (i1 >= j+1) ? accA[mf][nf][1]*r1*cj1 : 0.f;
            float v2 = (i2 >= j)   ? accA[mf][nf][2]*r2*cj0 : 0.f;
            float v3 = (i2 >= j+1) ? accA[mf][nf][3]*r2*cj1 : 0.f;
            uint32_t lw;
            uint32_t hw = pack2(v0, v1, lw);
            *(uint32_t*)(sm + SO_SH + (i1*136 + j)*2) = hw;
            *(uint32_t*)(sm + SO_SL + (i1*136 + j)*2) = lw;
            hw = pack2(v2, v3, lw);
            *(uint32_t*)(sm + SO_SH + (i2*136 + j)*2) = hw;
            *(uint32_t*)(sm + SO_SL + (i2*136 + j)*2) = lw;
        }
    }

    // ======== Phase B: out = S@V + (g^{i+1} Q)@T, two 128-col halves ====
    for (int h = 0; h < 2; h++) {
        int d0 = h*128;
        __syncthreads();
        #pragma unroll
        for (int l = 0; l < 8; l++) {
            int u = tid + l*256;
            int row = u >> 4, c8 = (u & 15)*8;
            size_t gp = (size_t)(b*SEQ + c0 + row)*DIM + d0 + c8;
            *(uint4*)(sm + SB_VH + (row*136 + c8)*2) = *(const uint4*)&g_Vh[gp];
            *(uint4*)(sm + SB_VL + (row*136 + c8)*2) = *(const uint4*)&g_Vl[gp];
        }
        __syncthreads();
        float acc[2][8][4] = {};
        // B1: S @ V
        for (int ks = 0; ks < 128; ks += 16) {
            int kc = ks + tg*2;
            uint32_t ah[2][4], al[2][4];
            #pragma unroll
            for (int mf = 0; mf < 2; mf++) {
                int r = wm*32 + mf*16 + gr;
                lda_dir(ah[mf], sm + SO_SH, r, kc, 136);
                lda_dir(al[mf], sm + SO_SL, r, kc, 136);
            }
            #pragma unroll
            for (int nfp = 0; nfp < 4; nfp++) {
                uint32_t bh[4], bl[4];
                ldsm4t(bh, baddr(smb + SB_VH, lane, ks, wn*64 + nfp*16, 136));
                ldsm4t(bl, baddr(smb + SB_VL, lane, ks, wn*64 + nfp*16, 136));
                #pragma unroll
                for (int mf = 0; mf < 2; mf++) {
                    mma16816(acc[mf][2*nfp],   ah[mf], bh);
                    mma16816(acc[mf][2*nfp+1], ah[mf], bh+2);
                    mma16816(acc[mf][2*nfp],   ah[mf], bl);
                    mma16816(acc[mf][2*nfp+1], ah[mf], bl+2);
                    mma16816(acc[mf][2*nfp],   al[mf], bh);
                    mma16816(acc[mf][2*nfp+1], al[mf], bh+2);
                }
            }
        }
        // B2: (g^{i+1} Q) @ T_prefix
        for (int e0 = 0; e0 < DIM; e0 += 64) {
            __syncthreads();
            #pragma unroll
            for (int l = 0; l < 8; l++) {
                int u = tid + l*256;              // Q: 128 rows x 16 float4
                int row = u >> 4, c4 = (u & 15)*4;
                float rG = rowg[row]*GAMMA;
                float4 q = *(const float4*)&g_Q[(size_t)(b*SEQ + c0 + row)*DIM + e0 + c4];
                uint32_t l01, l23;
                uint32_t h01 = pack2(q.x*rG, q.y*rG, l01);
                uint32_t h23 = pack2(q.z*rG, q.w*rG, l23);
                *(uint2*)(sm + SB_QH + (row*72 + c4)*2) = make_uint2(h01, h23);
                *(uint2*)(sm + SB_QL + (row*72 + c4)*2) = make_uint2(l01, l23);
            }
            #pragma unroll
            for (int l = 0; l < 4; l++) {
                int u = tid + l*256;              // T: 64 rows x 16 uint4
                int row = u >> 4, c8 = (u & 15)*8;
                size_t gp = (size_t)blk*65536 + (size_t)(e0 + row)*DIM + d0 + c8;
                *(uint4*)(sm + SB_TH + (row*136 + c8)*2) = *(const uint4*)&g_Th[gp];
                *(uint4*)(sm + SB_TL + (row*136 + c8)*2) = *(const uint4*)&g_Tl[gp];
            }
            __syncthreads();
            for (int ks = 0; ks < 64; ks += 16) {
                int kc = ks + tg*2;
                uint32_t ah[2][4], al[2][4];
                #pragma unroll
                for (int mf = 0; mf < 2; mf++) {
                    int r = wm*32 + mf*16 + gr;
                    lda_dir(ah[mf], sm + SB_QH, r, kc, 72);
                    lda_dir(al[mf], sm + SB_QL, r, kc, 72);
                }
                #pragma unroll
                for (int nfp = 0; nfp < 4; nfp++) {
                    uint32_t bh[4], bl[4];
                    ldsm4t(bh, baddr(smb + SB_TH, lane, ks, wn*64 + nfp*16, 136));
                    ldsm4t(bl, baddr(smb + SB_TL, lane, ks, wn*64 + nfp*16, 136));
                    #pragma unroll
                    for (int mf = 0; mf < 2; mf++) {
                        mma16816(acc[mf][2*nfp],   ah[mf], bh);
                        mma16816(acc[mf][2*nfp+1], ah[mf], bh+2);
                        mma16816(acc[mf][2*nfp],   ah[mf], bl);
                        mma16816(acc[mf][2*nfp+1], ah[mf], bl+2);
                        mma16816(acc[mf][2*nfp],   al[mf], bh);
                        mma16816(acc[mf][2*nfp+1], al[mf], bh+2);
                    }
                }
            }
        }
        // epilogue for this half
        #pragma unroll
        for (int mf = 0; mf < 2; mf++) {
            int i1 = wm*32 + mf*16 + gr;
            #pragma unroll
            for (int nf = 0; nf < 8; nf++) {
                int n = d0 + wn*64 + nf*8 + tg*2;
                *(float2*)&out[(size_t)(b*SEQ + c0 + i1)*DIM + n]     = make_float2(acc[mf][nf][0], acc[mf][nf][1]);
                *(float2*)&out[(size_t)(b*SEQ + c0 + i1 + 8)*DIM + n] = make_float2(acc[mf][nf][2], acc[mf][nf][3]);
            }
        }
    }
}

// -------------------------------------------------------------------------
extern "C" void kernel_launch(void* const* d_in, const int* in_sizes, int n_in,
                              void* d_out, int out_size) {
    const float* xq = (const float*)d_in[0];
    const float* xk = (const float*)d_in[1];
    const float* xv = (const float*)d_in[2];
    const float* Wq = (const float*)d_in[3];
    const float* bq = (const float*)d_in[4];
    const float* Wk = (const float*)d_in[5];
    const float* bk = (const float*)d_in[6];
    const float* Wv = (const float*)d_in[7];
    const float* bv = (const float*)d_in[8];
    float* out = (float*)d_out;

    static int once = 0;
    if (!once) {
        cudaFuncSetAttribute(k_tloc, cudaFuncAttributeMaxDynamicSharedMemorySize, SM_TLOC);
        cudaFuncSetAttribute(k_out,  cudaFuncAttributeMaxDynamicSharedMemorySize, SM_KOUT);
        once = 1;
    }

    k_init  <<<16, 256>>>();
    k_cvtW  <<<dim3(DIM, 3), 256>>>(Wq, Wk, Wv);
    k_proj_mma<<<dim3(ROWS_TOT/128, DIM/128, 3), 256>>>(xq, xk, xv, bq, bk, bv);
    k_sloc  <<<BB*NCH, 256>>>();
    k_spref <<<BB, 256>>>();
    k_rdenom<<<BB*NCH, 32>>>();
    k_tloc  <<<dim3(BB*NCH, 2, 2), 256, SM_TLOC>>>();
    k_tpref <<<BB*DIM*DIM/256, 256>>>();
    k_out   <<<BB*NCH, 256, SM_KOUT>>>(out);
}

// round 5
// speedup vs baseline: 2.4128x; 1.1160x over previous
#include <cuda_runtime.h>
#include <cuda_bf16.h>
#include <math.h>
#include <stdint.h>

#define BB 4
#define SEQ 4096
#define DIM 256
#define CHK 128
#define NCH (SEQ/CHK)      // 32
#define GAMMA 0.9865f
#define INV16 0.0625f
#define ROWS_TOT (BB*SEQ)  // 16384

// ---------------- scratch (device globals; no allocation) ----------------
__device__ float g_ic[SEQ];
__device__ float g_sloc[BB*NCH*DIM];
__device__ float g_sbd [BB*NCH*DIM];
__device__ float g_dinv[BB*SEQ];
__device__ float g_T[(size_t)BB*NCH*DIM*DIM];          // chunk-local T (fp32)
__device__ __nv_bfloat16 g_Th[(size_t)BB*NCH*DIM*DIM]; // prefix T hi
__device__ __nv_bfloat16 g_Tl[(size_t)BB*NCH*DIM*DIM]; // prefix T lo

__device__ __nv_bfloat16 g_Qh[BB*SEQ*DIM];
__device__ __nv_bfloat16 g_Ql[BB*SEQ*DIM];
__device__ __nv_bfloat16 g_Kh[BB*SEQ*DIM];
__device__ __nv_bfloat16 g_Kl[BB*SEQ*DIM];
__device__ __nv_bfloat16 g_Vh[BB*SEQ*DIM];
__device__ __nv_bfloat16 g_Vl[BB*SEQ*DIM];

__device__ __nv_bfloat16 g_Sh[(size_t)BB*SEQ*CHK];     // masked scores hi
__device__ __nv_bfloat16 g_Sl[(size_t)BB*SEQ*CHK];     // masked scores lo

__device__ __nv_bfloat16 g_Wth[3*DIM*DIM];             // W^T [n][k]
__device__ __nv_bfloat16 g_Wtl[3*DIM*DIM];

// ======================= helpers =========================================
__device__ __forceinline__ uint32_t smem_u32(const void* p) {
    uint32_t a;
    asm("{ .reg .u64 t; cvta.to.shared.u64 t, %1; cvt.u32.u64 %0, t; }" : "=r"(a) : "l"(p));
    return a;
}
__device__ __forceinline__ void mma16816(float* c, const uint32_t* a, const uint32_t* b) {
    asm volatile(
        "mma.sync.aligned.m16n8k16.row.col.f32.bf16.bf16.f32 "
        "{%0,%1,%2,%3}, {%4,%5,%6,%7}, {%8,%9}, {%0,%1,%2,%3};"
        : "+f"(c[0]), "+f"(c[1]), "+f"(c[2]), "+f"(c[3])
        : "r"(a[0]), "r"(a[1]), "r"(a[2]), "r"(a[3]), "r"(b[0]), "r"(b[1]));
}
__device__ __forceinline__ void ldsm4t(uint32_t* r, uint32_t a) {
    asm volatile("ldmatrix.sync.aligned.m8n8.x4.trans.shared.b16 {%0,%1,%2,%3}, [%4];"
        : "=r"(r[0]), "=r"(r[1]), "=r"(r[2]), "=r"(r[3]) : "r"(a));
}
__device__ __forceinline__ void lda_dir(uint32_t* a, const char* base, int row, int kc, int L) {
    a[0] = *(const uint32_t*)(base + (row*L + kc)*2);
    a[1] = *(const uint32_t*)(base + ((row+8)*L + kc)*2);
    a[2] = *(const uint32_t*)(base + (row*L + kc + 8)*2);
    a[3] = *(const uint32_t*)(base + ((row+8)*L + kc + 8)*2);
}
__device__ __forceinline__ uint32_t baddr(uint32_t base, int lane, int k0, int n0, int L) {
    int row = k0 + (lane & 7) + ((lane >> 3) & 1)*8;
    int col = n0 + ((lane >> 4) & 1)*8;
    return base + (uint32_t)(row*L + col)*2;
}
__device__ __forceinline__ uint32_t aaddr_t(uint32_t base, int lane, int m0, int k0, int L) {
    int row = k0 + (lane & 7) + ((lane >> 4) & 1)*8;
    int col = m0 + ((lane >> 3) & 1)*8;
    return base + (uint32_t)(row*L + col)*2;
}
__device__ __forceinline__ uint32_t pack2(float a, float b, uint32_t& lo) {
    __nv_bfloat16 ha = __float2bfloat16(a), hb = __float2bfloat16(b);
    __nv_bfloat162 hh; hh.x = ha; hh.y = hb;
    __nv_bfloat162 ll;
    ll.x = __float2bfloat16(a - __bfloat162float(ha));
    ll.y = __float2bfloat16(b - __bfloat162float(hb));
    lo = *(uint32_t*)&ll;
    return *(uint32_t*)&hh;
}
__device__ __forceinline__ void load8(float* f, const __nv_bfloat16* h, const __nv_bfloat16* l) {
    uint4 hv = *(const uint4*)h, lv = *(const uint4*)l;
    const __nv_bfloat162* hp = (const __nv_bfloat162*)&hv;
    const __nv_bfloat162* lp = (const __nv_bfloat162*)&lv;
    #pragma unroll
    for (int i = 0; i < 4; i++) {
        float2 a = __bfloat1622float2(hp[i]), bq = __bfloat1622float2(lp[i]);
        f[2*i] = a.x + bq.x; f[2*i+1] = a.y + bq.y;
    }
}

// ---------------- K0 -----------------------------------------------------
__global__ void k_init() {
    int j = blockIdx.x*256 + threadIdx.x;
    if (j < SEQ) {
        float lg = logf(GAMMA);
        float gp = expf((float)(j+1)*lg);
        g_ic[j] = rsqrtf((1.0f - gp)/(1.0f - GAMMA));
    }
}

__global__ void k_cvtW(const float* __restrict__ Wq, const float* __restrict__ Wk,
                       const float* __restrict__ Wv) {
    int mat = blockIdx.y;
    const float* W = (mat==0) ? Wq : (mat==1 ? Wk : Wv);
    int k = blockIdx.x, n = threadIdx.x;
    float w = W[k*DIM + n];
    __nv_bfloat16 h = __float2bfloat16(w);
    g_Wth[mat*DIM*DIM + n*DIM + k] = h;
    g_Wtl[mat*DIM*DIM + n*DIM + k] = __float2bfloat16(w - __bfloat162float(h));
}

// ---------------- K1: projection ------------------------------------------
#define PAD 40
__global__ void __launch_bounds__(256,2) k_proj_mma(
    const float* __restrict__ xq, const float* __restrict__ xk, const float* __restrict__ xv,
    const float* __restrict__ bq, const float* __restrict__ bk, const float* __restrict__ bv)
{
    __shared__ __nv_bfloat16 Ah[128*PAD];
    __shared__ __nv_bfloat16 Al[128*PAD];
    __shared__ __nv_bfloat16 Bh[128*PAD];
    __shared__ __nv_bfloat16 Bl[128*PAD];

    int tid = threadIdx.x;
    int warp = tid >> 5, lane = tid & 31;
    int wm = warp & 1, wn = warp >> 1;
    int gr = lane >> 2, tg = lane & 3;

    int mat = blockIdx.z;
    int m0 = blockIdx.x * 128;
    int n0 = blockIdx.y * 128;

    const float* X = (mat==0) ? xq : (mat==1 ? xk : xv);
    X += (size_t)m0*DIM;
    const __nv_bfloat16* Wh = g_Wth + mat*DIM*DIM + (size_t)n0*DIM;
    const __nv_bfloat16* Wl = g_Wtl + mat*DIM*DIM + (size_t)n0*DIM;
    const float* bias = (mat==0) ? bq : (mat==1 ? bk : bv);
    __nv_bfloat16* OH = ((mat==0) ? g_Qh : (mat==1 ? g_Kh : g_Vh)) + (size_t)m0*DIM;
    __nv_bfloat16* OL = ((mat==0) ? g_Ql : (mat==1 ? g_Kl : g_Vl)) + (size_t)m0*DIM;

    float acc[4][4][4] = {};

    for (int k0 = 0; k0 < DIM; k0 += 32) {
        #pragma unroll
        for (int l = 0; l < 4; l++) {
            int i = tid + l*256;
            int row = i >> 3, c4 = (i & 7)*4;
            float4 v = *(const float4*)&X[(size_t)row*DIM + k0 + c4];
            uint32_t l01, l23;
            uint32_t h01 = pack2(v.x, v.y, l01);
            uint32_t h23 = pack2(v.z, v.w, l23);
            *(uint2*)&Ah[row*PAD + c4] = make_uint2(h01, h23);
            *(uint2*)&Al[row*PAD + c4] = make_uint2(l01, l23);
        }
        #pragma unroll
        for (int l = 0; l < 2; l++) {
            int i = tid + l*256;
            int row = i >> 2, c8 = (i & 3)*8;
            *(uint4*)&Bh[row*PAD + c8] = *(const uint4*)&Wh[(size_t)row*DIM + k0 + c8];
            *(uint4*)&Bl[row*PAD + c8] = *(const uint4*)&Wl[(size_t)row*DIM + k0 + c8];
        }
        __syncthreads();

        #pragma unroll
        for (int ks = 0; ks < 32; ks += 16) {
            uint32_t ah[4][4], al[4][4];
            int kc = ks + tg*2;
            #pragma unroll
            for (int mf = 0; mf < 4; mf++) {
                int r0 = wm*64 + mf*16 + gr;
                ah[mf][0] = *(const uint32_t*)&Ah[r0*PAD + kc];
                ah[mf][1] = *(const uint32_t*)&Ah[(r0+8)*PAD + kc];
                ah[mf][2] = *(const uint32_t*)&Ah[r0*PAD + kc + 8];
                ah[mf][3] = *(const uint32_t*)&Ah[(r0+8)*PAD + kc + 8];
                al[mf][0] = *(const uint32_t*)&Al[r0*PAD + kc];
                al[mf][1] = *(const uint32_t*)&Al[(r0+8)*PAD + kc];
                al[mf][2] = *(const uint32_t*)&Al[r0*PAD + kc + 8];
                al[mf][3] = *(const uint32_t*)&Al[(r0+8)*PAD + kc + 8];
            }
            #pragma unroll
            for (int nf = 0; nf < 4; nf++) {
                int n = wn*32 + nf*8 + gr;
                uint32_t bh[2], bl[2];
                bh[0] = *(const uint32_t*)&Bh[n*PAD + kc];
                bh[1] = *(const uint32_t*)&Bh[n*PAD + kc + 8];
                bl[0] = *(const uint32_t*)&Bl[n*PAD + kc];
                bl[1] = *(const uint32_t*)&Bl[n*PAD + kc + 8];
                #pragma unroll
                for (int mf = 0; mf < 4; mf++) {
                    mma16816(acc[mf][nf], ah[mf], bh);
                    mma16816(acc[mf][nf], ah[mf], bl);
                    mma16816(acc[mf][nf], al[mf], bh);
                }
            }
        }
        __syncthreads();
    }

    #pragma unroll
    for (int nf = 0; nf < 4; nf++) {
        int col = n0 + wn*32 + nf*8 + tg*2;
        float b0 = bias[col], b1 = bias[col+1];
        #pragma unroll
        for (int mf = 0; mf < 4; mf++) {
            int row = wm*64 + mf*16 + gr;
            uint32_t lw0, lw1;
            uint32_t hw0 = pack2(acc[mf][nf][0] + b0, acc[mf][nf][1] + b1, lw0);
            uint32_t hw1 = pack2(acc[mf][nf][2] + b0, acc[mf][nf][3] + b1, lw1);
            *(uint32_t*)&OH[(size_t)row*DIM + col]     = hw0;
            *(uint32_t*)&OL[(size_t)row*DIM + col]     = lw0;
            *(uint32_t*)&OH[(size_t)(row+8)*DIM + col] = hw1;
            *(uint32_t*)&OL[(size_t)(row+8)*DIM + col] = lw1;
        }
    }
}

// ---------------- K2: per-chunk local decayed K/sqrt(c) sum --------------
__global__ void __launch_bounds__(256) k_sloc() {
    __shared__ float ics[CHK];
    int blk = blockIdx.x; int b = blk/NCH; int c = blk%NCH; int c0 = c*CHK;
    int d = threadIdx.x;
    if (d < CHK) ics[d] = g_ic[c0 + d];
    __syncthreads();
    float s = 0.f;
    for (int j = 0; j < CHK; j += 4) {
        float v[4];
        #pragma unroll
        for (int u = 0; u < 4; u++) {
            size_t p = (size_t)(b*SEQ + c0 + j + u)*DIM + d;
            v[u] = (__bfloat162float(g_Kh[p]) + __bfloat162float(g_Kl[p])) * ics[j+u];
        }
        s = (s*GAMMA + v[0])*GAMMA + v[1];
        s = (s*GAMMA + v[2])*GAMMA + v[3];
    }
    g_sloc[blk*DIM + d] = s;
}

// ---------------- K3: prefix combine --------------------------------------
__global__ void k_spref() {
    int b = blockIdx.x; int d = threadIdx.x;
    float v[NCH];
    #pragma unroll
    for (int c = 0; c < NCH; c++) v[c] = g_sloc[(b*NCH+c)*DIM + d];
    float gC = __expf(128.f*logf(GAMMA));
    float s = 0.f;
    #pragma unroll
    for (int c = 0; c < NCH; c++) { g_sbd[(b*NCH+c)*DIM + d] = s; s = s*gC + v[c]; }
}

// ---------------- K4: denom ------------------------------------------------
__global__ void k_rdenom() {   // grid BB*NCH, 32 threads
    int blk = blockIdx.x, b = blk >> 5, c = blk & 31, c0 = c*CHK;
    int lane = threadIdx.x;
    int d0 = lane*8;
    float w[8];
    *(float4*)&w[0] = *(const float4*)&g_sbd[blk*DIM + d0];
    *(float4*)&w[4] = *(const float4*)&g_sbd[blk*DIM + d0 + 4];
    for (int j = 0; j < CHK; j++) {
        int gj = c0 + j;
        size_t p = (size_t)(b*SEQ+gj)*DIM + d0;
        float ic = g_ic[gj];
        float kf[8], qf[8];
        load8(kf, &g_Kh[p], &g_Kl[p]);
        load8(qf, &g_Qh[p], &g_Ql[p]);
        float pr = 0.f;
        #pragma unroll
        for (int u = 0; u < 8; u++) {
            w[u] = w[u]*GAMMA + kf[u]*ic;
            pr += qf[u]*w[u];
        }
        #pragma unroll
        for (int o = 16; o > 0; o >>= 1) pr += __shfl_xor_sync(0xffffffffu, pr, o);
        if (lane == 0) g_dinv[b*SEQ + gj] = 1.0f / fmaxf(fabsf(pr*INV16), 1.0f);
    }
}

// ---------------- K5: chunk-local T via MMA, chunked smem ------------------
#define TLC_KH 0
#define TLC_KL 8704
#define TLC_VH 17408
#define TLC_VL 26112
#define SM_TLOC 34816
__global__ void __launch_bounds__(256,2) k_tloc() {
    extern __shared__ char sm[];
    __shared__ float w2[CHK];
    int tid = threadIdx.x, lane = tid & 31, warp = tid >> 5;
    int gr = lane >> 2, tg = lane & 3;
    int wm = warp >> 1, wn = warp & 1;
    int blk = blockIdx.x, b = blk >> 5, c = blk & 31, c0 = c*CHK;
    int d1t = blockIdx.y*128, d2t = blockIdx.z*128;

    if (tid < CHK) {
        int gj = c0 + tid;
        w2[tid] = __expf((float)(127-tid)*logf(GAMMA)) * g_ic[gj]*INV16*g_dinv[b*SEQ+gj];
    }
    __syncthreads();
    uint32_t smb = smem_u32(sm);
    float acc[2][8][4] = {};

    for (int j0 = 0; j0 < CHK; j0 += 32) {
        if (j0) __syncthreads();
        // stage wK (resplit): 32 rows x 128 cols
        #pragma unroll
        for (int l = 0; l < 2; l++) {
            int u = tid + l*256;
            int row = u >> 4, c8 = (u & 15)*8;
            size_t gp = (size_t)(b*SEQ + c0 + j0 + row)*DIM + d1t + c8;
            float f[8]; load8(f, &g_Kh[gp], &g_Kl[gp]);
            float w = w2[j0 + row];
            uint32_t hw[4], lw[4];
            #pragma unroll
            for (int i2 = 0; i2 < 4; i2++) hw[i2] = pack2(f[2*i2]*w, f[2*i2+1]*w, lw[i2]);
            *(uint4*)(sm + TLC_KH + (row*136 + c8)*2) = *(uint4*)hw;
            *(uint4*)(sm + TLC_KL + (row*136 + c8)*2) = *(uint4*)lw;
        }
        // stage V copy: 32 x 128
        #pragma unroll
        for (int l = 0; l < 2; l++) {
            int u = tid + l*256;
            int row = u >> 4, c8 = (u & 15)*8;
            size_t gp = (size_t)(b*SEQ + c0 + j0 + row)*DIM + d2t + c8;
            *(uint4*)(sm + TLC_VH + (row*136 + c8)*2) = *(const uint4*)&g_Vh[gp];
            *(uint4*)(sm + TLC_VL + (row*136 + c8)*2) = *(const uint4*)&g_Vl[gp];
        }
        __syncthreads();
        #pragma unroll
        for (int ks = 0; ks < 32; ks += 16) {
            uint32_t ah[2][4], al[2][4];
            #pragma unroll
            for (int mf = 0; mf < 2; mf++) {
                ldsm4t(ah[mf], aaddr_t(smb + TLC_KH, lane, wm*32 + mf*16, ks, 136));
                ldsm4t(al[mf], aaddr_t(smb + TLC_KL, lane, wm*32 + mf*16, ks, 136));
            }
            #pragma unroll
            for (int nfp = 0; nfp < 4; nfp++) {
                uint32_t bh[4], bl[4];
                ldsm4t(bh, baddr(smb + TLC_VH, lane, ks, wn*64 + nfp*16, 136));
                ldsm4t(bl, baddr(smb + TLC_VL, lane, ks, wn*64 + nfp*16, 136));
                #pragma unroll
                for (int mf = 0; mf < 2; mf++) {
                    mma16816(acc[mf][2*nfp],   ah[mf], bh);
                    mma16816(acc[mf][2*nfp+1], ah[mf], bh+2);
                    mma16816(acc[mf][2*nfp],   ah[mf], bl);
                    mma16816(acc[mf][2*nfp+1], ah[mf], bl+2);
                    mma16816(acc[mf][2*nfp],   al[mf], bh);
                    mma16816(acc[mf][2*nfp+1], al[mf], bh+2);
                }
            }
        }
    }
    #pragma unroll
    for (int mf = 0; mf < 2; mf++) {
        int d1 = d1t + wm*32 + mf*16 + gr;
        #pragma unroll
        for (int nf = 0; nf < 8; nf++) {
            int d2 = d2t + wn*64 + nf*8 + tg*2;
            *(float2*)&g_T[((size_t)blk*DIM + d1)*DIM + d2]     = make_float2(acc[mf][nf][0], acc[mf][nf][1]);
            *(float2*)&g_T[((size_t)blk*DIM + d1 + 8)*DIM + d2] = make_float2(acc[mf][nf][2], acc[mf][nf][3]);
        }
    }
}

// ---------------- K6: prefix of T -> bf16 hi/lo (prefetched) --------------
__global__ void k_tpref() {
    int idx = blockIdx.x*256 + threadIdx.x;
    int b   = idx >> 16;
    int off = idx & 65535;
    float v[NCH];
    #pragma unroll
    for (int c = 0; c < NCH; c++) v[c] = g_T[(((size_t)(b*NCH + c)) << 16) + off];
    float gC = __expf(128.f*logf(GAMMA));
    float t = 0.f;
    #pragma unroll
    for (int c = 0; c < NCH; c++) {
        size_t p = (((size_t)(b*NCH + c)) << 16) + off;
        __nv_bfloat16 h = __float2bfloat16(t);
        g_Th[p] = h;
        g_Tl[p] = __float2bfloat16(t - __bfloat162float(h));
        t = t*gC + v[c];
    }
}

// ---------------- K7a: S = mask(Q K^T) -> gmem bf16 hi/lo ------------------
#define KS_QH 0
#define KS_QL 10240
#define KS_KH 20480
#define KS_KL 30720
#define SM_KS 40960
__global__ void __launch_bounds__(256,2) k_S() {
    extern __shared__ char sm[];
    __shared__ float rowg[CHK];
    __shared__ float cw2[CHK];
    int tid = threadIdx.x, lane = tid & 31, warp = tid >> 5;
    int gr = lane >> 2, tg = lane & 3;
    int wm = warp >> 1, wn = warp & 1;
    int blk = blockIdx.x, b = blk >> 5, c = blk & 31, c0 = c*CHK;

    if (tid < CHK) {
        float lg = logf(GAMMA);
        rowg[tid] = __expf((float)tid * lg);
        int gj = c0 + tid;
        cw2[tid] = g_ic[gj]*INV16*g_dinv[b*SEQ+gj] * __expf(-(float)tid * lg);
    }
    __syncthreads();

    float accA[2][8][4] = {};
    for (int e0 = 0; e0 < DIM; e0 += 32) {
        if (e0) __syncthreads();
        #pragma unroll
        for (int l = 0; l < 2; l++) {
            int u = tid + l*256;
            int row = u >> 2, c8 = (u & 3)*8;
            size_t gp = (size_t)(b*SEQ + c0 + row)*DIM + e0 + c8;
            *(uint4*)(sm + KS_QH + (row*PAD + c8)*2) = *(const uint4*)&g_Qh[gp];
            *(uint4*)(sm + KS_QL + (row*PAD + c8)*2) = *(const uint4*)&g_Ql[gp];
            *(uint4*)(sm + KS_KH + (row*PAD + c8)*2) = *(const uint4*)&g_Kh[gp];
            *(uint4*)(sm + KS_KL + (row*PAD + c8)*2) = *(const uint4*)&g_Kl[gp];
        }
        __syncthreads();
        #pragma unroll
        for (int ks = 0; ks < 32; ks += 16) {
            int kc = ks + tg*2;
            uint32_t ah[2][4], al[2][4];
            #pragma unroll
            for (int mf = 0; mf < 2; mf++) {
                int r = wm*32 + mf*16 + gr;
                lda_dir(ah[mf], sm + KS_QH, r, kc, PAD);
                lda_dir(al[mf], sm + KS_QL, r, kc, PAD);
            }
            #pragma unroll
            for (int nf = 0; nf < 8; nf++) {
                int n = wn*64 + nf*8 + gr;
                uint32_t bh[2], bl[2];
                bh[0] = *(const uint32_t*)(sm + KS_KH + (n*PAD + kc)*2);
                bh[1] = *(const uint32_t*)(sm + KS_KH + (n*PAD + kc + 8)*2);
                bl[0] = *(const uint32_t*)(sm + KS_KL + (n*PAD + kc)*2);
                bl[1] = *(const uint32_t*)(sm + KS_KL + (n*PAD + kc + 8)*2);
                #pragma unroll
                for (int mf = 0; mf < 2; mf++) {
                    mma16816(accA[mf][nf], ah[mf], bh);
                    mma16816(accA[mf][nf], ah[mf], bl);
                    mma16816(accA[mf][nf], al[mf], bh);
                }
            }
        }
    }
    // mask + decay, write to gmem
    #pragma unroll
    for (int mf = 0; mf < 2; mf++) {
        int i1 = wm*32 + mf*16 + gr, i2 = i1 + 8;
        float r1 = rowg[i1], r2 = rowg[i2];
        #pragma unroll
        for (int nf = 0; nf < 8; nf++) {
            int j = wn*64 + nf*8 + tg*2;
            float cj0 = cw2[j], cj1 = cw2[j+1];
            float v0 = (i1 >= j)   ? accA[mf][nf][0]*r1*cj0 : 0.f;
            float v1 = (i1 >= j+1) ? accA[mf][nf][1]*r1*cj1 : 0.f;
            float v2 = (i2 >= j)   ? accA[mf][nf][2]*r2*cj0 : 0.f;
            float v3 = (i2 >= j+1) ? accA[mf][nf][3]*r2*cj1 : 0.f;
            uint32_t lw;
            uint32_t hw = pack2(v0, v1, lw);
            *(uint32_t*)&g_Sh[(size_t)(blk*CHK + i1)*CHK + j] = hw;
            *(uint32_t*)&g_Sl[(size_t)(blk*CHK + i1)*CHK + j] = lw;
            hw = pack2(v2, v3, lw);
            *(uint32_t*)&g_Sh[(size_t)(blk*CHK + i2)*CHK + j] = hw;
            *(uint32_t*)&g_Sl[(size_t)(blk*CHK + i2)*CHK + j] = lw;
        }
    }
}

// ---------------- K7b: out = S@V + (g^{i+1} Q)@T, per N-half ---------------
#define KB_AH 0
#define KB_AL 10240
#define KB_BH 20480
#define KB_BL 29184
#define SM_KB 37888
__global__ void __launch_bounds__(256,2) k_B(float* __restrict__ out) {
    extern __shared__ char sm[];
    __shared__ float rowGn[CHK];
    int tid = threadIdx.x, lane = tid & 31, warp = tid >> 5;
    int gr = lane >> 2, tg = lane & 3;
    int wm = warp >> 1, wn = warp & 1;
    int blk = blockIdx.x, b = blk >> 5, c = blk & 31, c0 = c*CHK;
    int d0 = blockIdx.y * 128;

    if (tid < CHK) rowGn[tid] = __expf((float)(tid+1) * logf(GAMMA));
    __syncthreads();
    uint32_t smb = smem_u32(sm);
    float acc[2][8][4] = {};

    // ---- B1: S @ V ----
    for (int k0 = 0; k0 < CHK; k0 += 32) {
        if (k0) __syncthreads();
        #pragma unroll
        for (int l = 0; l < 2; l++) {
            int u = tid + l*256;
            int row = u >> 2, c8 = (u & 3)*8;
            size_t gp = (size_t)(blk*CHK + row)*CHK + k0 + c8;
            *(uint4*)(sm + KB_AH + (row*PAD + c8)*2) = *(const uint4*)&g_Sh[gp];
            *(uint4*)(sm + KB_AL + (row*PAD + c8)*2) = *(const uint4*)&g_Sl[gp];
        }
        #pragma unroll
        for (int l = 0; l < 2; l++) {
            int u = tid + l*256;
            int row = u >> 4, c8 = (u & 15)*8;
            size_t gp = (size_t)(b*SEQ + c0 + k0 + row)*DIM + d0 + c8;
            *(uint4*)(sm + KB_BH + (row*136 + c8)*2) = *(const uint4*)&g_Vh[gp];
            *(uint4*)(sm + KB_BL + (row*136 + c8)*2) = *(const uint4*)&g_Vl[gp];
        }
        __syncthreads();
        #pragma unroll
        for (int ks = 0; ks < 32; ks += 16) {
            int kc = ks + tg*2;
            uint32_t ah[2][4], al[2][4];
            #pragma unroll
            for (int mf = 0; mf < 2; mf++) {
                int r = wm*32 + mf*16 + gr;
                lda_dir(ah[mf], sm + KB_AH, r, kc, PAD);
                lda_dir(al[mf], sm + KB_AL, r, kc, PAD);
            }
            #pragma unroll
            for (int nfp = 0; nfp < 4; nfp++) {
                uint32_t bh[4], bl[4];
                ldsm4t(bh, baddr(smb + KB_BH, lane, ks, wn*64 + nfp*16, 136));
                ldsm4t(bl, baddr(smb + KB_BL, lane, ks, wn*64 + nfp*16, 136));
                #pragma unroll
                for (int mf = 0; mf < 2; mf++) {
                    mma16816(acc[mf][2*nfp],   ah[mf], bh);
                    mma16816(acc[mf][2*nfp+1], ah[mf], bh+2);
                    mma16816(acc[mf][2*nfp],   ah[mf], bl);
                    mma16816(acc[mf][2*nfp+1], ah[mf], bl+2);
                    mma16816(acc[mf][2*nfp],   al[mf], bh);
                    mma16816(acc[mf][2*nfp+1], al[mf], bh+2);
                }
            }
        }
    }

    // ---- B2: (g^{i+1} Q) @ T_prefix ----
    for (int e0 = 0; e0 < DIM; e0 += 32) {
        __syncthreads();
        #pragma unroll
        for (int l = 0; l < 2; l++) {
            int u = tid + l*256;
            int row = u >> 2, c8 = (u & 3)*8;
            size_t gp = (size_t)(b*SEQ + c0 + row)*DIM + e0 + c8;
            float f[8]; load8(f, &g_Qh[gp], &g_Ql[gp]);
            float rG = rowGn[row];
            uint32_t hw[4], lw[4];
            #pragma unroll
            for (int i2 = 0; i2 < 4; i2++) hw[i2] = pack2(f[2*i2]*rG, f[2*i2+1]*rG, lw[i2]);
            *(uint4*)(sm + KB_AH + (row*PAD + c8)*2) = *(uint4*)hw;
            *(uint4*)(sm + KB_AL + (row*PAD + c8)*2) = *(uint4*)lw;
        }
        #pragma unroll
        for (int l = 0; l < 2; l++) {
            int u = tid + l*256;
            int row = u >> 4, c8 = (u & 15)*8;
            size_t gp = (size_t)blk*65536 + (size_t)(e0 + row)*DIM + d0 + c8;
            *(uint4*)(sm + KB_BH + (row*136 + c8)*2) = *(const uint4*)&g_Th[gp];
            *(uint4*)(sm + KB_BL + (row*136 + c8)*2) = *(const uint4*)&g_Tl[gp];
        }
        __syncthreads();
        #pragma unroll
        for (int ks = 0; ks < 32; ks += 16) {
            int kc = ks + tg*2;
            uint32_t ah[2][4], al[2][4];
            #pragma unroll
            for (int mf = 0; mf < 2; mf++) {
                int r = wm*32 + mf*16 + gr;
                lda_dir(ah[mf], sm + KB_AH, r, kc, PAD);
                lda_dir(al[mf], sm + KB_AL, r, kc, PAD);
            }
            #pragma unroll
            for (int nfp = 0; nfp < 4; nfp++) {
                uint32_t bh[4], bl[4];
                ldsm4t(bh, baddr(smb + KB_BH, lane, ks, wn*64 + nfp*16, 136));
                ldsm4t(bl, baddr(smb + KB_BL, lane, ks, wn*64 + nfp*16, 136));
                #pragma unroll
                for (int mf = 0; mf < 2; mf++) {
                    mma16816(acc[mf][2*nfp],   ah[mf], bh);
                    mma16816(acc[mf][2*nfp+1], ah[mf], bh+2);
                    mma16816(acc[mf][2*nfp],   ah[mf], bl);
                    mma16816(acc[mf][2*nfp+1], ah[mf], bl+2);
                    mma16816(acc[mf][2*nfp],   al[mf], bh);
                    mma16816(acc[mf][2*nfp+1], al[mf], bh+2);
                }
            }
        }
    }

    // epilogue
    #pragma unroll
    for (int mf = 0; mf < 2; mf++) {
        int i1 = wm*32 + mf*16 + gr;
        #pragma unroll
        for (int nf = 0; nf < 8; nf++) {
            int n = d0 + wn*64 + nf*8 + tg*2;
            *(float2*)&out[(size_t)(b*SEQ + c0 + i1)*DIM + n]     = make_float2(acc[mf][nf][0], acc[mf][nf][1]);
            *(float2*)&out[(size_t)(b*SEQ + c0 + i1 + 8)*DIM + n] = make_float2(acc[mf][nf][2], acc[mf][nf][3]);
        }
    }
}

// -------------------------------------------------------------------------
extern "C" void kernel_launch(void* const* d_in, const int* in_sizes, int n_in,
                              void* d_out, int out_size) {
    const float* xq = (const float*)d_in[0];
    const float* xk = (const float*)d_in[1];
    const float* xv = (const float*)d_in[2];
    const float* Wq = (const float*)d_in[3];
    const float* bq = (const float*)d_in[4];
    const float* Wk = (const float*)d_in[5];
    const float* bk = (const float*)d_in[6];
    const float* Wv = (const float*)d_in[7];
    const float* bv = (const float*)d_in[8];
    float* out = (float*)d_out;

    k_init  <<<16, 256>>>();
    k_cvtW  <<<dim3(DIM, 3), 256>>>(Wq, Wk, Wv);
    k_proj_mma<<<dim3(ROWS_TOT/128, DIM/128, 3), 256>>>(xq, xk, xv, bq, bk, bv);
    k_sloc  <<<BB*NCH, 256>>>();
    k_spref <<<BB, 256>>>();
    k_rdenom<<<BB*NCH, 32>>>();
    k_tloc  <<<dim3(BB*NCH, 2, 2), 256, SM_TLOC>>>();
    k_tpref <<<BB*DIM*DIM/256, 256>>>();
    k_S     <<<BB*NCH, 256, SM_KS>>>();
    k_B     <<<dim3(BB*NCH, 2), 256, SM_KB>>>(out);
}

// round 6
// speedup vs baseline: 3.8193x; 1.5829x over previous
#include <cuda_runtime.h>
#include <cuda_bf16.h>
#include <math.h>
#include <stdint.h>

#define BB 4
#define SEQ 4096
#define DIM 256
#define CHK 128
#define NCH (SEQ/CHK)      // 32
#define GAMMA 0.9865f
#define INV16 0.0625f
#define ROWS_TOT (BB*SEQ)  // 16384

// ---------------- scratch ----------------
__device__ float g_ic[SEQ];
__device__ float g_sloc[BB*NCH*DIM];
__device__ float g_sbd [BB*NCH*DIM];
__device__ float g_dinv[BB*SEQ];
__device__ float g_T[(size_t)BB*NCH*DIM*DIM];
__device__ __nv_bfloat16 g_Th[(size_t)BB*NCH*DIM*DIM];
__device__ __nv_bfloat16 g_Tl[(size_t)BB*NCH*DIM*DIM];

__device__ __nv_bfloat16 g_Qh[BB*SEQ*DIM];
__device__ __nv_bfloat16 g_Ql[BB*SEQ*DIM];
__device__ __nv_bfloat16 g_Kh[BB*SEQ*DIM];
__device__ __nv_bfloat16 g_Kl[BB*SEQ*DIM];
__device__ __nv_bfloat16 g_Vh[BB*SEQ*DIM];
__device__ __nv_bfloat16 g_Vl[BB*SEQ*DIM];

__device__ __nv_bfloat16 g_Sh[(size_t)BB*SEQ*CHK];
__device__ __nv_bfloat16 g_Sl[(size_t)BB*SEQ*CHK];

__device__ __nv_bfloat16 g_Wth[3*DIM*DIM];             // W^T [n][k]
__device__ __nv_bfloat16 g_Wtl[3*DIM*DIM];

// ======================= helpers =========================================
__device__ __forceinline__ uint32_t smem_u32(const void* p) {
    uint32_t a;
    asm("{ .reg .u64 t; cvta.to.shared.u64 t, %1; cvt.u32.u64 %0, t; }" : "=r"(a) : "l"(p));
    return a;
}
__device__ __forceinline__ void mma16816(float* c, const uint32_t* a, const uint32_t* b) {
    asm volatile(
        "mma.sync.aligned.m16n8k16.row.col.f32.bf16.bf16.f32 "
        "{%0,%1,%2,%3}, {%4,%5,%6,%7}, {%8,%9}, {%0,%1,%2,%3};"
        : "+f"(c[0]), "+f"(c[1]), "+f"(c[2]), "+f"(c[3])
        : "r"(a[0]), "r"(a[1]), "r"(a[2]), "r"(a[3]), "r"(b[0]), "r"(b[1]));
}
__device__ __forceinline__ void ldsm4(uint32_t* r, uint32_t a) {
    asm volatile("ldmatrix.sync.aligned.m8n8.x4.shared.b16 {%0,%1,%2,%3}, [%4];"
        : "=r"(r[0]), "=r"(r[1]), "=r"(r[2]), "=r"(r[3]) : "r"(a));
}
__device__ __forceinline__ void ldsm4t(uint32_t* r, uint32_t a) {
    asm volatile("ldmatrix.sync.aligned.m8n8.x4.trans.shared.b16 {%0,%1,%2,%3}, [%4];"
        : "=r"(r[0]), "=r"(r[1]), "=r"(r[2]), "=r"(r[3]) : "r"(a));
}
// A-frag (m16 x k16) from row-major [m][k] bf16 buffer, non-trans ldmatrix
__device__ __forceinline__ uint32_t addr_am(uint32_t base, int lane, int m0, int k0, int L) {
    int row = m0 + (lane & 7) + ((lane >> 3) & 1)*8;
    int col = k0 + ((lane >> 4) & 1)*8;
    return base + (uint32_t)(row*L + col)*2;
}
// B-frags for n-groups (n0..+7, n0+8..+15) from row-major [n][k]: regs {b0(n0),b1(n0),b0(n0+8),b1(n0+8)}
__device__ __forceinline__ uint32_t addr_bn(uint32_t base, int lane, int n0, int k0, int L) {
    int row = n0 + (lane & 7) + ((lane >> 4) & 1)*8;
    int col = k0 + ((lane >> 3) & 1)*8;
    return base + (uint32_t)(row*L + col)*2;
}
// ldmatrix.trans B-frag (k16 x n16) from [k rows][n cols] buffer
__device__ __forceinline__ uint32_t baddr(uint32_t base, int lane, int k0, int n0, int L) {
    int row = k0 + (lane & 7) + ((lane >> 3) & 1)*8;
    int col = n0 + ((lane >> 4) & 1)*8;
    return base + (uint32_t)(row*L + col)*2;
}
// ldmatrix.trans A-frag (m16 x k16) from [k rows][m cols] buffer
__device__ __forceinline__ uint32_t aaddr_t(uint32_t base, int lane, int m0, int k0, int L) {
    int row = k0 + (lane & 7) + ((lane >> 4) & 1)*8;
    int col = m0 + ((lane >> 3) & 1)*8;
    return base + (uint32_t)(row*L + col)*2;
}
__device__ __forceinline__ uint32_t pack2(float a, float b, uint32_t& lo) {
    __nv_bfloat16 ha = __float2bfloat16(a), hb = __float2bfloat16(b);
    __nv_bfloat162 hh; hh.x = ha; hh.y = hb;
    __nv_bfloat162 ll;
    ll.x = __float2bfloat16(a - __bfloat162float(ha));
    ll.y = __float2bfloat16(b - __bfloat162float(hb));
    lo = *(uint32_t*)&ll;
    return *(uint32_t*)&hh;
}
__device__ __forceinline__ void load8(float* f, const __nv_bfloat16* h, const __nv_bfloat16* l) {
    uint4 hv = *(const uint4*)h, lv = *(const uint4*)l;
    const __nv_bfloat162* hp = (const __nv_bfloat162*)&hv;
    const __nv_bfloat162* lp = (const __nv_bfloat162*)&lv;
    #pragma unroll
    for (int i = 0; i < 4; i++) {
        float2 a = __bfloat1622float2(hp[i]), bq = __bfloat1622float2(lp[i]);
        f[2*i] = a.x + bq.x; f[2*i+1] = a.y + bq.y;
    }
}

// ---------------- K0 -----------------------------------------------------
__global__ void k_init() {
    int j = blockIdx.x*256 + threadIdx.x;
    if (j < SEQ) {
        float lg = logf(GAMMA);
        float gp = expf((float)(j+1)*lg);
        g_ic[j] = rsqrtf((1.0f - gp)/(1.0f - GAMMA));
    }
}

__global__ void k_cvtW(const float* __restrict__ Wq, const float* __restrict__ Wk,
                       const float* __restrict__ Wv) {
    int mat = blockIdx.y;
    const float* W = (mat==0) ? Wq : (mat==1 ? Wk : Wv);
    int k = blockIdx.x, n = threadIdx.x;
    float w = W[k*DIM + n];
    __nv_bfloat16 h = __float2bfloat16(w);
    g_Wth[mat*DIM*DIM + n*DIM + k] = h;
    g_Wtl[mat*DIM*DIM + n*DIM + k] = __float2bfloat16(w - __bfloat162float(h));
}

// ---------------- K1: projection (+ fused sloc reduction for K) -----------
#define PAD 40
__global__ void __launch_bounds__(256,2) k_proj_mma(
    const float* __restrict__ xq, const float* __restrict__ xk, const float* __restrict__ xv,
    const float* __restrict__ bq, const float* __restrict__ bk, const float* __restrict__ bv)
{
    __shared__ alignas(16) __nv_bfloat16 Ah[128*PAD];
    __shared__ alignas(16) __nv_bfloat16 Al[128*PAD];
    __shared__ alignas(16) __nv_bfloat16 Bh[128*PAD];
    __shared__ alignas(16) __nv_bfloat16 Bl[128*PAD];
    __shared__ float sl[128];
    __shared__ float wdec[128];

    int tid = threadIdx.x;
    int warp = tid >> 5, lane = tid & 31;
    int wm = warp & 1, wn = warp >> 1;
    int gr = lane >> 2, tg = lane & 3;

    int mat = blockIdx.z;
    int m0 = blockIdx.x * 128;
    int n0 = blockIdx.y * 128;

    if (tid < 128) {
        sl[tid] = 0.f;
        wdec[tid] = __expf((float)(127-tid)*logf(GAMMA)) * g_ic[(m0+tid) & (SEQ-1)];
    }

    const float* X = (mat==0) ? xq : (mat==1 ? xk : xv);
    X += (size_t)m0*DIM;
    const __nv_bfloat16* Wh = g_Wth + mat*DIM*DIM + (size_t)n0*DIM;
    const __nv_bfloat16* Wl = g_Wtl + mat*DIM*DIM + (size_t)n0*DIM;
    const float* bias = (mat==0) ? bq : (mat==1 ? bk : bv);
    __nv_bfloat16* OH = ((mat==0) ? g_Qh : (mat==1 ? g_Kh : g_Vh)) + (size_t)m0*DIM;
    __nv_bfloat16* OL = ((mat==0) ? g_Ql : (mat==1 ? g_Kl : g_Vl)) + (size_t)m0*DIM;

    uint32_t sAh = smem_u32(Ah), sAl = smem_u32(Al);
    uint32_t sBh = smem_u32(Bh), sBl = smem_u32(Bl);

    float acc[4][4][4] = {};

    for (int k0 = 0; k0 < DIM; k0 += 32) {
        #pragma unroll
        for (int l = 0; l < 4; l++) {
            int i = tid + l*256;
            int row = i >> 3, c4 = (i & 7)*4;
            float4 v = *(const float4*)&X[(size_t)row*DIM + k0 + c4];
            uint32_t l01, l23;
            uint32_t h01 = pack2(v.x, v.y, l01);
            uint32_t h23 = pack2(v.z, v.w, l23);
            *(uint2*)&Ah[row*PAD + c4] = make_uint2(h01, h23);
            *(uint2*)&Al[row*PAD + c4] = make_uint2(l01, l23);
        }
        #pragma unroll
        for (int l = 0; l < 2; l++) {
            int i = tid + l*256;
            int row = i >> 2, c8 = (i & 3)*8;
            *(uint4*)&Bh[row*PAD + c8] = *(const uint4*)&Wh[(size_t)row*DIM + k0 + c8];
            *(uint4*)&Bl[row*PAD + c8] = *(const uint4*)&Wl[(size_t)row*DIM + k0 + c8];
        }
        __syncthreads();

        #pragma unroll
        for (int ks = 0; ks < 32; ks += 16) {
            uint32_t ah[4][4], al[4][4];
            #pragma unroll
            for (int mf = 0; mf < 4; mf++) {
                ldsm4(ah[mf], addr_am(sAh, lane, wm*64 + mf*16, ks, PAD));
                ldsm4(al[mf], addr_am(sAl, lane, wm*64 + mf*16, ks, PAD));
            }
            uint32_t bh[2][4], bl[2][4];
            #pragma unroll
            for (int p = 0; p < 2; p++) {
                ldsm4(bh[p], addr_bn(sBh, lane, wn*32 + p*16, ks, PAD));
                ldsm4(bl[p], addr_bn(sBl, lane, wn*32 + p*16, ks, PAD));
            }
            #pragma unroll
            for (int nf = 0; nf < 4; nf++) {
                const uint32_t* pbh = &bh[nf>>1][(nf&1)*2];
                const uint32_t* pbl = &bl[nf>>1][(nf&1)*2];
                #pragma unroll
                for (int mf = 0; mf < 4; mf++) {
                    mma16816(acc[mf][nf], ah[mf], pbh);
                    mma16816(acc[mf][nf], ah[mf], pbl);
                    mma16816(acc[mf][nf], al[mf], pbh);
                }
            }
        }
        __syncthreads();
    }

    #pragma unroll
    for (int nf = 0; nf < 4; nf++) {
        int col = n0 + wn*32 + nf*8 + tg*2;
        float b0 = bias[col], b1 = bias[col+1];
        float s0 = 0.f, s1 = 0.f;
        #pragma unroll
        for (int mf = 0; mf < 4; mf++) {
            int row = wm*64 + mf*16 + gr;
            float v00 = acc[mf][nf][0] + b0, v01 = acc[mf][nf][1] + b1;
            float v10 = acc[mf][nf][2] + b0, v11 = acc[mf][nf][3] + b1;
            uint32_t lw0, lw1;
            uint32_t hw0 = pack2(v00, v01, lw0);
            uint32_t hw1 = pack2(v10, v11, lw1);
            *(uint32_t*)&OH[(size_t)row*DIM + col]     = hw0;
            *(uint32_t*)&OL[(size_t)row*DIM + col]     = lw0;
            *(uint32_t*)&OH[(size_t)(row+8)*DIM + col] = hw1;
            *(uint32_t*)&OL[(size_t)(row+8)*DIM + col] = lw1;
            if (mat == 1) {
                s0 += wdec[row]*v00 + wdec[row+8]*v10;
                s1 += wdec[row]*v01 + wdec[row+8]*v11;
            }
        }
        if (mat == 1) {
            int cl = wn*32 + nf*8 + tg*2;
            atomicAdd(&sl[cl], s0);
            atomicAdd(&sl[cl+1], s1);
        }
    }
    if (mat == 1) {
        __syncthreads();
        if (tid < 128) g_sloc[blockIdx.x*DIM + n0 + tid] = sl[tid];
    }
}

// ---------------- K3: prefix combine --------------------------------------
__global__ void k_spref() {
    int b = blockIdx.x; int d = threadIdx.x;
    float v[NCH];
    #pragma unroll
    for (int c = 0; c < NCH; c++) v[c] = g_sloc[(b*NCH+c)*DIM + d];
    float gC = __expf(128.f*logf(GAMMA));
    float s = 0.f;
    #pragma unroll
    for (int c = 0; c < NCH; c++) { g_sbd[(b*NCH+c)*DIM + d] = s; s = s*gC + v[c]; }
}

// ---------------- K7a: S = mask(Q K^T), fused denom ------------------------
#define KS_QH 0
#define KS_QL 10240
#define KS_KH 20480
#define KS_KL 30720
#define SM_KS 40960
__global__ void __launch_bounds__(256,2) k_S() {
    extern __shared__ char sm[];
    __shared__ float rowg[CHK];
    __shared__ float cw[CHK];
    __shared__ float rsum[CHK];
    __shared__ float dv[CHK];
    int tid = threadIdx.x, lane = tid & 31, warp = tid >> 5;
    int gr = lane >> 2, tg = lane & 3;
    int wm = warp >> 1, wn = warp & 1;
    int blk = blockIdx.x, b = blk >> 5, c = blk & 31, c0 = c*CHK;
    float lg = logf(GAMMA);

    if (tid < CHK) {
        rowg[tid] = __expf((float)tid * lg);
        cw[tid]   = g_ic[c0 + tid]*INV16 * __expf(-(float)tid * lg);
        rsum[tid] = 0.f;
    }
    __syncthreads();

    // cross-chunk term of the row sum: gamma^{i+1} * INV16 * (Q_i . sbd)
    {
        int row = tid >> 1, half = tid & 1;
        int dbase = half*128;
        size_t qp = (size_t)(b*SEQ + c0 + row)*DIM + dbase;
        const float* sb = &g_sbd[blk*DIM + dbase];
        float part = 0.f;
        #pragma unroll
        for (int d = 0; d < 128; d += 8) {
            float qf[8]; load8(qf, &g_Qh[qp + d], &g_Ql[qp + d]);
            float4 s1 = *(const float4*)&sb[d], s2 = *(const float4*)&sb[d+4];
            part += qf[0]*s1.x + qf[1]*s1.y + qf[2]*s1.z + qf[3]*s1.w
                  + qf[4]*s2.x + qf[5]*s2.y + qf[6]*s2.z + qf[7]*s2.w;
        }
        atomicAdd(&rsum[row], part * __expf((float)(row+1)*lg) * INV16);
    }

    uint32_t smb = smem_u32(sm);
    float accA[2][8][4] = {};
    for (int e0 = 0; e0 < DIM; e0 += 32) {
        if (e0) __syncthreads();
        #pragma unroll
        for (int l = 0; l < 2; l++) {
            int u = tid + l*256;
            int row = u >> 2, c8 = (u & 3)*8;
            size_t gp = (size_t)(b*SEQ + c0 + row)*DIM + e0 + c8;
            *(uint4*)(sm + KS_QH + (row*PAD + c8)*2) = *(const uint4*)&g_Qh[gp];
            *(uint4*)(sm + KS_QL + (row*PAD + c8)*2) = *(const uint4*)&g_Ql[gp];
            *(uint4*)(sm + KS_KH + (row*PAD + c8)*2) = *(const uint4*)&g_Kh[gp];
            *(uint4*)(sm + KS_KL + (row*PAD + c8)*2) = *(const uint4*)&g_Kl[gp];
        }
        __syncthreads();
        #pragma unroll
        for (int ks = 0; ks < 32; ks += 16) {
            uint32_t ah[2][4], al[2][4];
            #pragma unroll
            for (int mf = 0; mf < 2; mf++) {
                ldsm4(ah[mf], addr_am(smb + KS_QH, lane, wm*32 + mf*16, ks, PAD));
                ldsm4(al[mf], addr_am(smb + KS_QL, lane, wm*32 + mf*16, ks, PAD));
            }
            uint32_t bh[4][4], bl[4][4];
            #pragma unroll
            for (int p = 0; p < 4; p++) {
                ldsm4(bh[p], addr_bn(smb + KS_KH, lane, wn*64 + p*16, ks, PAD));
                ldsm4(bl[p], addr_bn(smb + KS_KL, lane, wn*64 + p*16, ks, PAD));
            }
            #pragma unroll
            for (int nf = 0; nf < 8; nf++) {
                const uint32_t* pbh = &bh[nf>>1][(nf&1)*2];
                const uint32_t* pbl = &bl[nf>>1][(nf&1)*2];
                #pragma unroll
                for (int mf = 0; mf < 2; mf++) {
                    mma16816(accA[mf][nf], ah[mf], pbh);
                    mma16816(accA[mf][nf], ah[mf], pbl);
                    mma16816(accA[mf][nf], al[mf], pbh);
                }
            }
        }
    }

    // mask + decay (no dinv yet), accumulate row sums
    #pragma unroll
    for (int mf = 0; mf < 2; mf++) {
        int i1 = wm*32 + mf*16 + gr, i2 = i1 + 8;
        float r1 = rowg[i1], r2 = rowg[i2];
        float rs1 = 0.f, rs2 = 0.f;
        #pragma unroll
        for (int nf = 0; nf < 8; nf++) {
            int j = wn*64 + nf*8 + tg*2;
            float cj0 = cw[j], cj1 = cw[j+1];
            accA[mf][nf][0] = (i1 >= j)   ? accA[mf][nf][0]*r1*cj0 : 0.f;
            accA[mf][nf][1] = (i1 >= j+1) ? accA[mf][nf][1]*r1*cj1 : 0.f;
            accA[mf][nf][2] = (i2 >= j)   ? accA[mf][nf][2]*r2*cj0 : 0.f;
            accA[mf][nf][3] = (i2 >= j+1) ? accA[mf][nf][3]*r2*cj1 : 0.f;
            rs1 += accA[mf][nf][0] + accA[mf][nf][1];
            rs2 += accA[mf][nf][2] + accA[mf][nf][3];
        }
        atomicAdd(&rsum[i1], rs1);
        atomicAdd(&rsum[i2], rs2);
    }
    __syncthreads();
    if (tid < CHK) {
        float d = 1.0f / fmaxf(fabsf(rsum[tid]), 1.0f);
        dv[tid] = d;
        g_dinv[b*SEQ + c0 + tid] = d;
    }
    __syncthreads();

    // apply column dinv, write S
    #pragma unroll
    for (int mf = 0; mf < 2; mf++) {
        int i1 = wm*32 + mf*16 + gr, i2 = i1 + 8;
        #pragma unroll
        for (int nf = 0; nf < 8; nf++) {
            int j = wn*64 + nf*8 + tg*2;
            float dj0 = dv[j], dj1 = dv[j+1];
            uint32_t lw;
            uint32_t hw = pack2(accA[mf][nf][0]*dj0, accA[mf][nf][1]*dj1, lw);
            *(uint32_t*)&g_Sh[(size_t)(blk*CHK + i1)*CHK + j] = hw;
            *(uint32_t*)&g_Sl[(size_t)(blk*CHK + i1)*CHK + j] = lw;
            hw = pack2(accA[mf][nf][2]*dj0, accA[mf][nf][3]*dj1, lw);
            *(uint32_t*)&g_Sh[(size_t)(blk*CHK + i2)*CHK + j] = hw;
            *(uint32_t*)&g_Sl[(size_t)(blk*CHK + i2)*CHK + j] = lw;
        }
    }
}

// ---------------- K5: chunk-local T via MMA --------------------------------
#define TLC_KH 0
#define TLC_KL 8704
#define TLC_VH 17408
#define TLC_VL 26112
#define SM_TLOC 34816
__global__ void __launch_bounds__(256,2) k_tloc() {
    extern __shared__ char sm[];
    __shared__ float w2[CHK];
    int tid = threadIdx.x, lane = tid & 31, warp = tid >> 5;
    int gr = lane >> 2, tg = lane & 3;
    int wm = warp >> 1, wn = warp & 1;
    int blk = blockIdx.x, b = blk >> 5, c = blk & 31, c0 = c*CHK;
    int d1t = blockIdx.y*128, d2t = blockIdx.z*128;

    if (tid < CHK) {
        int gj = c0 + tid;
        w2[tid] = __expf((float)(127-tid)*logf(GAMMA)) * g_ic[gj]*INV16*g_dinv[b*SEQ+gj];
    }
    __syncthreads();
    uint32_t smb = smem_u32(sm);
    float acc[2][8][4] = {};

    for (int j0 = 0; j0 < CHK; j0 += 32) {
        if (j0) __syncthreads();
        #pragma unroll
        for (int l = 0; l < 2; l++) {
            int u = tid + l*256;
            int row = u >> 4, c8 = (u & 15)*8;
            size_t gp = (size_t)(b*SEQ + c0 + j0 + row)*DIM + d1t + c8;
            float f[8]; load8(f, &g_Kh[gp], &g_Kl[gp]);
            float w = w2[j0 + row];
            uint32_t hw[4], lw[4];
            #pragma unroll
            for (int i2 = 0; i2 < 4; i2++) hw[i2] = pack2(f[2*i2]*w, f[2*i2+1]*w, lw[i2]);
            *(uint4*)(sm + TLC_KH + (row*136 + c8)*2) = *(uint4*)hw;
            *(uint4*)(sm + TLC_KL + (row*136 + c8)*2) = *(uint4*)lw;
        }
        #pragma unroll
        for (int l = 0; l < 2; l++) {
            int u = tid + l*256;
            int row = u >> 4, c8 = (u & 15)*8;
            size_t gp = (size_t)(b*SEQ + c0 + j0 + row)*DIM + d2t + c8;
            *(uint4*)(sm + TLC_VH + (row*136 + c8)*2) = *(const uint4*)&g_Vh[gp];
            *(uint4*)(sm + TLC_VL + (row*136 + c8)*2) = *(const uint4*)&g_Vl[gp];
        }
        __syncthreads();
        #pragma unroll
        for (int ks = 0; ks < 32; ks += 16) {
            uint32_t ah[2][4], al[2][4];
            #pragma unroll
            for (int mf = 0; mf < 2; mf++) {
                ldsm4t(ah[mf], aaddr_t(smb + TLC_KH, lane, wm*32 + mf*16, ks, 136));
                ldsm4t(al[mf], aaddr_t(smb + TLC_KL, lane, wm*32 + mf*16, ks, 136));
            }
            #pragma unroll
            for (int nfp = 0; nfp < 4; nfp++) {
                uint32_t bh[4], bl[4];
                ldsm4t(bh, baddr(smb + TLC_VH, lane, ks, wn*64 + nfp*16, 136));
                ldsm4t(bl, baddr(smb + TLC_VL, lane, ks, wn*64 + nfp*16, 136));
                #pragma unroll
                for (int mf = 0; mf < 2; mf++) {
                    mma16816(acc[mf][2*nfp],   ah[mf], bh);
                    mma16816(acc[mf][2*nfp+1], ah[mf], bh+2);
                    mma16816(acc[mf][2*nfp],   ah[mf], bl);
                    mma16816(acc[mf][2*nfp+1], ah[mf], bl+2);
                    mma16816(acc[mf][2*nfp],   al[mf], bh);
                    mma16816(acc[mf][2*nfp+1], al[mf], bh+2);
                }
            }
        }
    }
    #pragma unroll
    for (int mf = 0; mf < 2; mf++) {
        int d1 = d1t + wm*32 + mf*16 + gr;
        #pragma unroll
        for (int nf = 0; nf < 8; nf++) {
            int d2 = d2t + wn*64 + nf*8 + tg*2;
            *(float2*)&g_T[((size_t)blk*DIM + d1)*DIM + d2]     = make_float2(acc[mf][nf][0], acc[mf][nf][1]);
            *(float2*)&g_T[((size_t)blk*DIM + d1 + 8)*DIM + d2] = make_float2(acc[mf][nf][2], acc[mf][nf][3]);
        }
    }
}

// ---------------- K6: prefix of T -> bf16 hi/lo ----------------------------
__global__ void k_tpref() {
    int idx = blockIdx.x*256 + threadIdx.x;
    int b   = idx >> 16;
    int off = idx & 65535;
    float v[NCH];
    #pragma unroll
    for (int c = 0; c < NCH; c++) v[c] = g_T[(((size_t)(b*NCH + c)) << 16) + off];
    float gC = __expf(128.f*logf(GAMMA));
    float t = 0.f;
    #pragma unroll
    for (int c = 0; c < NCH; c++) {
        size_t p = (((size_t)(b*NCH + c)) << 16) + off;
        __nv_bfloat16 h = __float2bfloat16(t);
        g_Th[p] = h;
        g_Tl[p] = __float2bfloat16(t - __bfloat162float(h));
        t = t*gC + v[c];
    }
}

// ---------------- K7b: out = S@V + (g^{i+1} Q)@T ---------------------------
#define KB_AH 0
#define KB_AL 10240
#define KB_BH 20480
#define KB_BL 29184
#define SM_KB 37888
__global__ void __launch_bounds__(256,2) k_B(float* __restrict__ out) {
    extern __shared__ char sm[];
    __shared__ float rowGn[CHK];
    int tid = threadIdx.x, lane = tid & 31, warp = tid >> 5;
    int gr = lane >> 2, tg = lane & 3;
    int wm = warp >> 1, wn = warp & 1;
    int blk = blockIdx.x, b = blk >> 5, c = blk & 31, c0 = c*CHK;
    int d0 = blockIdx.y * 128;

    if (tid < CHK) rowGn[tid] = __expf((float)(tid+1) * logf(GAMMA));
    __syncthreads();
    uint32_t smb = smem_u32(sm);
    float acc[2][8][4] = {};

    // ---- B1: S @ V ----
    for (int k0 = 0; k0 < CHK; k0 += 32) {
        if (k0) __syncthreads();
        #pragma unroll
        for (int l = 0; l < 2; l++) {
            int u = tid + l*256;
            int row = u >> 2, c8 = (u & 3)*8;
            size_t gp = (size_t)(blk*CHK + row)*CHK + k0 + c8;
            *(uint4*)(sm + KB_AH + (row*PAD + c8)*2) = *(const uint4*)&g_Sh[gp];
            *(uint4*)(sm + KB_AL + (row*PAD + c8)*2) = *(const uint4*)&g_Sl[gp];
        }
        #pragma unroll
        for (int l = 0; l < 2; l++) {
            int u = tid + l*256;
            int row = u >> 4, c8 = (u & 15)*8;
            size_t gp = (size_t)(b*SEQ + c0 + k0 + row)*DIM + d0 + c8;
            *(uint4*)(sm + KB_BH + (row*136 + c8)*2) = *(const uint4*)&g_Vh[gp];
            *(uint4*)(sm + KB_BL + (row*136 + c8)*2) = *(const uint4*)&g_Vl[gp];
        }
        __syncthreads();
        #pragma unroll
        for (int ks = 0; ks < 32; ks += 16) {
            uint32_t ah[2][4], al[2][4];
            #pragma unroll
            for (int mf = 0; mf < 2; mf++) {
                ldsm4(ah[mf], addr_am(smb + KB_AH, lane, wm*32 + mf*16, ks, PAD));
                ldsm4(al[mf], addr_am(smb + KB_AL, lane, wm*32 + mf*16, ks, PAD));
            }
            #pragma unroll
            for (int nfp = 0; nfp < 4; nfp++) {
                uint32_t bh[4], bl[4];
                ldsm4t(bh, baddr(smb + KB_BH, lane, ks, wn*64 + nfp*16, 136));
                ldsm4t(bl, baddr(smb + KB_BL, lane, ks, wn*64 + nfp*16, 136));
                #pragma unroll
                for (int mf = 0; mf < 2; mf++) {
                    mma16816(acc[mf][2*nfp],   ah[mf], bh);
                    mma16816(acc[mf][2*nfp+1], ah[mf], bh+2);
                    mma16816(acc[mf][2*nfp],   ah[mf], bl);
                    mma16816(acc[mf][2*nfp+1], ah[mf], bl+2);
                    mma16816(acc[mf][2*nfp],   al[mf], bh);
                    mma16816(acc[mf][2*nfp+1], al[mf], bh+2);
                }
            }
        }
    }

    // ---- B2: (g^{i+1} Q) @ T_prefix ----
    for (int e0 = 0; e0 < DIM; e0 += 32) {
        __syncthreads();
        #pragma unroll
        for (int l = 0; l < 2; l++) {
            int u = tid + l*256;
            int row = u >> 2, c8 = (u & 3)*8;
            size_t gp = (size_t)(b*SEQ + c0 + row)*DIM + e0 + c8;
            float f[8]; load8(f, &g_Qh[gp], &g_Ql[gp]);
            float rG = rowGn[row];
            uint32_t hw[4], lw[4];
            #pragma unroll
            for (int i2 = 0; i2 < 4; i2++) hw[i2] = pack2(f[2*i2]*rG, f[2*i2+1]*rG, lw[i2]);
            *(uint4*)(sm + KB_AH + (row*PAD + c8)*2) = *(uint4*)hw;
            *(uint4*)(sm + KB_AL + (row*PAD + c8)*2) = *(uint4*)lw;
        }
        #pragma unroll
        for (int l = 0; l < 2; l++) {
            int u = tid + l*256;
            int row = u >> 4, c8 = (u & 15)*8;
            size_t gp = (size_t)blk*65536 + (size_t)(e0 + row)*DIM + d0 + c8;
            *(uint4*)(sm + KB_BH + (row*136 + c8)*2) = *(const uint4*)&g_Th[gp];
            *(uint4*)(sm + KB_BL + (row*136 + c8)*2) = *(const uint4*)&g_Tl[gp];
        }
        __syncthreads();
        #pragma unroll
        for (int ks = 0; ks < 32; ks += 16) {
            uint32_t ah[2][4], al[2][4];
            #pragma unroll
            for (int mf = 0; mf < 2; mf++) {
                ldsm4(ah[mf], addr_am(smb + KB_AH, lane, wm*32 + mf*16, ks, PAD));
                ldsm4(al[mf], addr_am(smb + KB_AL, lane, wm*32 + mf*16, ks, PAD));
            }
            #pragma unroll
            for (int nfp = 0; nfp < 4; nfp++) {
                uint32_t bh[4], bl[4];
                ldsm4t(bh, baddr(smb + KB_BH, lane, ks, wn*64 + nfp*16, 136));
                ldsm4t(bl, baddr(smb + KB_BL, lane, ks, wn*64 + nfp*16, 136));
                #pragma unroll
                for (int mf = 0; mf < 2; mf++) {
                    mma16816(acc[mf][2*nfp],   ah[mf], bh);
                    mma16816(acc[mf][2*nfp+1], ah[mf], bh+2);
                    mma16816(acc[mf][2*nfp],   ah[mf], bl);
                    mma16816(acc[mf][2*nfp+1], ah[mf], bl+2);
                    mma16816(acc[mf][2*nfp],   al[mf], bh);
                    mma16816(acc[mf][2*nfp+1], al[mf], bh+2);
                }
            }
        }
    }

    #pragma unroll
    for (int mf = 0; mf < 2; mf++) {
        int i1 = wm*32 + mf*16 + gr;
        #pragma unroll
        for (int nf = 0; nf < 8; nf++) {
            int n = d0 + wn*64 + nf*8 + tg*2;
            *(float2*)&out[(size_t)(b*SEQ + c0 + i1)*DIM + n]     = make_float2(acc[mf][nf][0], acc[mf][nf][1]);
            *(float2*)&out[(size_t)(b*SEQ + c0 + i1 + 8)*DIM + n] = make_float2(acc[mf][nf][2], acc[mf][nf][3]);
        }
    }
}

// -------------------------------------------------------------------------
extern "C" void kernel_launch(void* const* d_in, const int* in_sizes, int n_in,
                              void* d_out, int out_size) {
    const float* xq = (const float*)d_in[0];
    const float* xk = (const float*)d_in[1];
    const float* xv = (const float*)d_in[2];
    const float* Wq = (const float*)d_in[3];
    const float* bq = (const float*)d_in[4];
    const float* Wk = (const float*)d_in[5];
    const float* bk = (const float*)d_in[6];
    const float* Wv = (const float*)d_in[7];
    const float* bv = (const float*)d_in[8];
    float* out = (float*)d_out;

    k_init  <<<16, 256>>>();
    k_cvtW  <<<dim3(DIM, 3), 256>>>(Wq, Wk, Wv);
    k_proj_mma<<<dim3(ROWS_TOT/128, DIM/128, 3), 256>>>(xq, xk, xv, bq, bk, bv);
    k_spref <<<BB, 256>>>();
    k_S     <<<BB*NCH, 256, SM_KS>>>();
    k_tloc  <<<dim3(BB*NCH, 2, 2), 256, SM_TLOC>>>();
    k_tpref <<<BB*DIM*DIM/256, 256>>>();
    k_B     <<<dim3(BB*NCH, 2), 256, SM_KB>>>(out);
}

// round 7
// speedup vs baseline: 3.8608x; 1.0109x over previous
#include <cuda_runtime.h>
#include <cuda_bf16.h>
#include <math.h>
#include <stdint.h>

#define BB 4
#define SEQ 4096
#define DIM 256
#define CHK 128
#define NCH (SEQ/CHK)      // 32
#define GAMMA 0.9865f
#define INV16 0.0625f
#define ROWS_TOT (BB*SEQ)  // 16384
#define PAD 40

// ---------------- scratch ----------------
__device__ float g_ic[SEQ];
__device__ float g_sloc[BB*NCH*DIM];
__device__ float g_sbd [BB*NCH*DIM];
__device__ float g_dinv[BB*SEQ];
__device__ float g_T[(size_t)BB*NCH*DIM*DIM];
__device__ __nv_bfloat16 g_Th[(size_t)BB*NCH*DIM*DIM];
__device__ __nv_bfloat16 g_Tl[(size_t)BB*NCH*DIM*DIM];

__device__ __nv_bfloat16 g_Qh[BB*SEQ*DIM];
__device__ __nv_bfloat16 g_Ql[BB*SEQ*DIM];
__device__ __nv_bfloat16 g_Kh[BB*SEQ*DIM];
__device__ __nv_bfloat16 g_Kl[BB*SEQ*DIM];
__device__ __nv_bfloat16 g_Vh[BB*SEQ*DIM];
__device__ __nv_bfloat16 g_Vl[BB*SEQ*DIM];

__device__ __nv_bfloat16 g_Sh[(size_t)BB*SEQ*CHK];
__device__ __nv_bfloat16 g_Sl[(size_t)BB*SEQ*CHK];

__device__ __nv_bfloat16 g_Wth[3*DIM*DIM];             // W^T [n][k]
__device__ __nv_bfloat16 g_Wtl[3*DIM*DIM];

// ======================= helpers =========================================
__device__ __forceinline__ uint32_t smem_u32(const void* p) {
    uint32_t a;
    asm("{ .reg .u64 t; cvta.to.shared.u64 t, %1; cvt.u32.u64 %0, t; }" : "=r"(a) : "l"(p));
    return a;
}
__device__ __forceinline__ void cpa(uint32_t d, const void* s) {
    asm volatile("cp.async.cg.shared.global [%0], [%1], 16;" :: "r"(d), "l"(s));
}
#define CPA_COMMIT asm volatile("cp.async.commit_group;" ::: "memory")
#define CPA_WAIT0  asm volatile("cp.async.wait_group 0;" ::: "memory")

__device__ __forceinline__ void mma16816(float* c, const uint32_t* a, const uint32_t* b) {
    asm volatile(
        "mma.sync.aligned.m16n8k16.row.col.f32.bf16.bf16.f32 "
        "{%0,%1,%2,%3}, {%4,%5,%6,%7}, {%8,%9}, {%0,%1,%2,%3};"
        : "+f"(c[0]), "+f"(c[1]), "+f"(c[2]), "+f"(c[3])
        : "r"(a[0]), "r"(a[1]), "r"(a[2]), "r"(a[3]), "r"(b[0]), "r"(b[1]));
}
__device__ __forceinline__ void ldsm4(uint32_t* r, uint32_t a) {
    asm volatile("ldmatrix.sync.aligned.m8n8.x4.shared.b16 {%0,%1,%2,%3}, [%4];"
        : "=r"(r[0]), "=r"(r[1]), "=r"(r[2]), "=r"(r[3]) : "r"(a));
}
__device__ __forceinline__ void ldsm4t(uint32_t* r, uint32_t a) {
    asm volatile("ldmatrix.sync.aligned.m8n8.x4.trans.shared.b16 {%0,%1,%2,%3}, [%4];"
        : "=r"(r[0]), "=r"(r[1]), "=r"(r[2]), "=r"(r[3]) : "r"(a));
}
__device__ __forceinline__ uint32_t addr_am(uint32_t base, int lane, int m0, int k0, int L) {
    int row = m0 + (lane & 7) + ((lane >> 3) & 1)*8;
    int col = k0 + ((lane >> 4) & 1)*8;
    return base + (uint32_t)(row*L + col)*2;
}
__device__ __forceinline__ uint32_t addr_bn(uint32_t base, int lane, int n0, int k0, int L) {
    int row = n0 + (lane & 7) + ((lane >> 4) & 1)*8;
    int col = k0 + ((lane >> 3) & 1)*8;
    return base + (uint32_t)(row*L + col)*2;
}
__device__ __forceinline__ uint32_t baddr(uint32_t base, int lane, int k0, int n0, int L) {
    int row = k0 + (lane & 7) + ((lane >> 3) & 1)*8;
    int col = n0 + ((lane >> 4) & 1)*8;
    return base + (uint32_t)(row*L + col)*2;
}
__device__ __forceinline__ uint32_t aaddr_t(uint32_t base, int lane, int m0, int k0, int L) {
    int row = k0 + (lane & 7) + ((lane >> 4) & 1)*8;
    int col = m0 + ((lane >> 3) & 1)*8;
    return base + (uint32_t)(row*L + col)*2;
}
__device__ __forceinline__ uint32_t pack2(float a, float b, uint32_t& lo) {
    __nv_bfloat16 ha = __float2bfloat16(a), hb = __float2bfloat16(b);
    __nv_bfloat162 hh; hh.x = ha; hh.y = hb;
    __nv_bfloat162 ll;
    ll.x = __float2bfloat16(a - __bfloat162float(ha));
    ll.y = __float2bfloat16(b - __bfloat162float(hb));
    lo = *(uint32_t*)&ll;
    return *(uint32_t*)&hh;
}
__device__ __forceinline__ void load8(float* f, const __nv_bfloat16* h, const __nv_bfloat16* l) {
    uint4 hv = *(const uint4*)h, lv = *(const uint4*)l;
    const __nv_bfloat162* hp = (const __nv_bfloat162*)&hv;
    const __nv_bfloat162* lp = (const __nv_bfloat162*)&lv;
    #pragma unroll
    for (int i = 0; i < 4; i++) {
        float2 a = __bfloat1622float2(hp[i]), bq = __bfloat1622float2(lp[i]);
        f[2*i] = a.x + bq.x; f[2*i+1] = a.y + bq.y;
    }
}
__device__ __forceinline__ void load8r(float* f, uint4 hv, uint4 lv) {
    const __nv_bfloat162* hp = (const __nv_bfloat162*)&hv;
    const __nv_bfloat162* lp = (const __nv_bfloat162*)&lv;
    #pragma unroll
    for (int i = 0; i < 4; i++) {
        float2 a = __bfloat1622float2(hp[i]), bq = __bfloat1622float2(lp[i]);
        f[2*i] = a.x + bq.x; f[2*i+1] = a.y + bq.y;
    }
}

// ---------------- K0: W split + ic ---------------------------------------
__global__ void k_prep(const float* __restrict__ Wq, const float* __restrict__ Wk,
                       const float* __restrict__ Wv) {
    int mat = blockIdx.y;
    const float* W = (mat==0) ? Wq : (mat==1 ? Wk : Wv);
    int k = blockIdx.x, n = threadIdx.x;
    float w = W[k*DIM + n];
    __nv_bfloat16 h = __float2bfloat16(w);
    g_Wth[mat*DIM*DIM + n*DIM + k] = h;
    g_Wtl[mat*DIM*DIM + n*DIM + k] = __float2bfloat16(w - __bfloat162float(h));
    if (mat == 0 && k < 16) {
        int j = k*256 + n;
        float lg = logf(GAMMA);
        float gp = expf((float)(j+1)*lg);
        g_ic[j] = rsqrtf((1.0f - gp)/(1.0f - GAMMA));
    }
}

// ---------------- K1: projection (cp.async W, reg-prefetch X) -------------
#define P_XH 0
#define P_XL 10240
#define P_W(buf) (20480 + (buf)*20480)
#define SM_PROJ 61440
__global__ void __launch_bounds__(256,2) k_proj_mma(
    const float* __restrict__ xq, const float* __restrict__ xk, const float* __restrict__ xv,
    const float* __restrict__ bq, const float* __restrict__ bk, const float* __restrict__ bv)
{
    extern __shared__ char sm[];
    __shared__ float sl[128];
    __shared__ float wdec[128];

    int tid = threadIdx.x;
    int warp = tid >> 5, lane = tid & 31;
    int wm = warp & 1, wn = warp >> 1;
    int gr = lane >> 2, tg = lane & 3;

    int mat = blockIdx.z;
    int m0 = blockIdx.x * 128;
    int n0 = blockIdx.y * 128;

    if (tid < 128) {
        sl[tid] = 0.f;
        wdec[tid] = __expf((float)(127-tid)*logf(GAMMA)) * g_ic[(m0+tid) & (SEQ-1)];
    }

    const float* X = (mat==0) ? xq : (mat==1 ? xk : xv);
    X += (size_t)m0*DIM;
    const __nv_bfloat16* Wh = g_Wth + mat*DIM*DIM + (size_t)n0*DIM;
    const __nv_bfloat16* Wl = g_Wtl + mat*DIM*DIM + (size_t)n0*DIM;
    const float* bias = (mat==0) ? bq : (mat==1 ? bk : bv);
    __nv_bfloat16* OH = ((mat==0) ? g_Qh : (mat==1 ? g_Kh : g_Vh)) + (size_t)m0*DIM;
    __nv_bfloat16* OL = ((mat==0) ? g_Ql : (mat==1 ? g_Kl : g_Vl)) + (size_t)m0*DIM;

    uint32_t smb = smem_u32(sm);
    float acc[4][4][4] = {};
    float4 xr[4];

    // prologue: X regs stage 0, W cp.async stage 0
    #pragma unroll
    for (int l = 0; l < 4; l++) {
        int i = tid + l*256;
        int row = i >> 3, c4 = (i & 7)*4;
        xr[l] = *(const float4*)&X[(size_t)row*DIM + c4];
    }
    #pragma unroll
    for (int l = 0; l < 2; l++) {
        int i = tid + l*256;
        int row = i >> 2, c8 = (i & 3)*8;
        cpa(smb + P_W(0) + (row*PAD + c8)*2,         &Wh[(size_t)row*DIM + c8]);
        cpa(smb + P_W(0) + 10240 + (row*PAD + c8)*2, &Wl[(size_t)row*DIM + c8]);
    }
    CPA_COMMIT;

    for (int st = 0; st < 8; st++) {
        int k0 = st*32;
        CPA_WAIT0;
        __syncthreads();
        // STS converted X (single buffer)
        #pragma unroll
        for (int l = 0; l < 4; l++) {
            int i = tid + l*256;
            int row = i >> 3, c4 = (i & 7)*4;
            uint32_t l01, l23;
            uint32_t h01 = pack2(xr[l].x, xr[l].y, l01);
            uint32_t h23 = pack2(xr[l].z, xr[l].w, l23);
            *(uint2*)(sm + P_XH + (row*PAD + c4)*2) = make_uint2(h01, h23);
            *(uint2*)(sm + P_XL + (row*PAD + c4)*2) = make_uint2(l01, l23);
        }
        if (st < 7) {
            int kn = k0 + 32;
            #pragma unroll
            for (int l = 0; l < 2; l++) {
                int i = tid + l*256;
                int row = i >> 2, c8 = (i & 3)*8;
                cpa(smb + P_W((st+1)&1) + (row*PAD + c8)*2,         &Wh[(size_t)row*DIM + kn + c8]);
                cpa(smb + P_W((st+1)&1) + 10240 + (row*PAD + c8)*2, &Wl[(size_t)row*DIM + kn + c8]);
            }
            CPA_COMMIT;
        }
        __syncthreads();
        if (st < 7) {
            int kn = k0 + 32;
            #pragma unroll
            for (int l = 0; l < 4; l++) {
                int i = tid + l*256;
                int row = i >> 3, c4 = (i & 7)*4;
                xr[l] = *(const float4*)&X[(size_t)row*DIM + kn + c4];
            }
        }
        uint32_t sBh = smb + P_W(st&1), sBl = sBh + 10240;
        #pragma unroll
        for (int ks = 0; ks < 32; ks += 16) {
            uint32_t ah[4][4], al[4][4];
            #pragma unroll
            for (int mf = 0; mf < 4; mf++) {
                ldsm4(ah[mf], addr_am(smb + P_XH, lane, wm*64 + mf*16, ks, PAD));
                ldsm4(al[mf], addr_am(smb + P_XL, lane, wm*64 + mf*16, ks, PAD));
            }
            uint32_t bh[2][4], bl[2][4];
            #pragma unroll
            for (int p = 0; p < 2; p++) {
                ldsm4(bh[p], addr_bn(sBh, lane, wn*32 + p*16, ks, PAD));
                ldsm4(bl[p], addr_bn(sBl, lane, wn*32 + p*16, ks, PAD));
            }
            #pragma unroll
            for (int nf = 0; nf < 4; nf++) {
                const uint32_t* pbh = &bh[nf>>1][(nf&1)*2];
                const uint32_t* pbl = &bl[nf>>1][(nf&1)*2];
                #pragma unroll
                for (int mf = 0; mf < 4; mf++) {
                    mma16816(acc[mf][nf], ah[mf], pbh);
                    mma16816(acc[mf][nf], ah[mf], pbl);
                    mma16816(acc[mf][nf], al[mf], pbh);
                }
            }
        }
    }

    #pragma unroll
    for (int nf = 0; nf < 4; nf++) {
        int col = n0 + wn*32 + nf*8 + tg*2;
        float b0 = bias[col], b1 = bias[col+1];
        float s0 = 0.f, s1 = 0.f;
        #pragma unroll
        for (int mf = 0; mf < 4; mf++) {
            int row = wm*64 + mf*16 + gr;
            float v00 = acc[mf][nf][0] + b0, v01 = acc[mf][nf][1] + b1;
            float v10 = acc[mf][nf][2] + b0, v11 = acc[mf][nf][3] + b1;
            uint32_t lw0, lw1;
            uint32_t hw0 = pack2(v00, v01, lw0);
            uint32_t hw1 = pack2(v10, v11, lw1);
            *(uint32_t*)&OH[(size_t)row*DIM + col]     = hw0;
            *(uint32_t*)&OL[(size_t)row*DIM + col]     = lw0;
            *(uint32_t*)&OH[(size_t)(row+8)*DIM + col] = hw1;
            *(uint32_t*)&OL[(size_t)(row+8)*DIM + col] = lw1;
            if (mat == 1) {
                s0 += wdec[row]*v00 + wdec[row+8]*v10;
                s1 += wdec[row]*v01 + wdec[row+8]*v11;
            }
        }
        if (mat == 1) {
            int cl = wn*32 + nf*8 + tg*2;
            atomicAdd(&sl[cl], s0);
            atomicAdd(&sl[cl+1], s1);
        }
    }
    if (mat == 1) {
        __syncthreads();
        if (tid < 128) g_sloc[blockIdx.x*DIM + n0 + tid] = sl[tid];
    }
}

// ---------------- K3: prefix combine --------------------------------------
__global__ void k_spref() {   // grid BB*8, 32 threads
    int b = blockIdx.x >> 3;
    int d = (blockIdx.x & 7)*32 + threadIdx.x;
    float v[NCH];
    #pragma unroll
    for (int c = 0; c < NCH; c++) v[c] = g_sloc[(b*NCH+c)*DIM + d];
    float gC = __expf(128.f*logf(GAMMA));
    float s = 0.f;
    #pragma unroll
    for (int c = 0; c < NCH; c++) { g_sbd[(b*NCH+c)*DIM + d] = s; s = s*gC + v[c]; }
}

// ---------------- K7a: S = mask(Q K^T), fused denom, cp.async -------------
#define S_STG 40960
#define S_QH 0
#define S_QL 10240
#define S_KH 20480
#define S_KL 30720
#define SM_KS (2*S_STG)
__global__ void __launch_bounds__(256,2) k_S() {
    extern __shared__ char sm[];
    __shared__ float rowg[CHK];
    __shared__ float cw[CHK];
    __shared__ float rsum[CHK];
    __shared__ float dv[CHK];
    int tid = threadIdx.x, lane = tid & 31, warp = tid >> 5;
    int gr = lane >> 2, tg = lane & 3;
    int wm = warp >> 1, wn = warp & 1;
    int blk = blockIdx.x, b = blk >> 5, c = blk & 31, c0 = c*CHK;
    float lg = logf(GAMMA);
    uint32_t smb = smem_u32(sm);

    const __nv_bfloat16 *Qh = g_Qh + (size_t)(b*SEQ + c0)*DIM;
    const __nv_bfloat16 *Ql = g_Ql + (size_t)(b*SEQ + c0)*DIM;
    const __nv_bfloat16 *Kh = g_Kh + (size_t)(b*SEQ + c0)*DIM;
    const __nv_bfloat16 *Kl = g_Kl + (size_t)(b*SEQ + c0)*DIM;

    // issue stage 0 immediately
    #pragma unroll
    for (int l = 0; l < 2; l++) {
        int u = tid + l*256;
        int row = u >> 2, c8 = (u & 3)*8;
        uint32_t so = (uint32_t)(row*PAD + c8)*2;
        size_t go = (size_t)row*DIM + c8;
        cpa(smb + S_QH + so, Qh + go);
        cpa(smb + S_QL + so, Ql + go);
        cpa(smb + S_KH + so, Kh + go);
        cpa(smb + S_KL + so, Kl + go);
    }
    CPA_COMMIT;

    if (tid < CHK) {
        rowg[tid] = __expf((float)tid * lg);
        cw[tid]   = g_ic[c0 + tid]*INV16 * __expf(-(float)tid * lg);
        rsum[tid] = 0.f;
    }
    __syncthreads();

    // cross-chunk row-sum term (overlaps stage-0 cp.async)
    {
        int row = tid >> 1, half = tid & 1;
        int dbase = half*128;
        size_t qp = (size_t)row*DIM + dbase;
        const float* sb = &g_sbd[blk*DIM + dbase];
        float part = 0.f;
        #pragma unroll
        for (int d = 0; d < 128; d += 8) {
            float qf[8]; load8(qf, Qh + qp + d, Ql + qp + d);
            float4 s1 = *(const float4*)&sb[d], s2 = *(const float4*)&sb[d+4];
            part += qf[0]*s1.x + qf[1]*s1.y + qf[2]*s1.z + qf[3]*s1.w
                  + qf[4]*s2.x + qf[5]*s2.y + qf[6]*s2.z + qf[7]*s2.w;
        }
        atomicAdd(&rsum[row], part * __expf((float)(row+1)*lg) * INV16);
    }

    float accA[2][8][4] = {};
    for (int st = 0; st < 8; st++) {
        CPA_WAIT0;
        __syncthreads();
        if (st < 7) {
            int en = (st+1)*32;
            uint32_t bb = smb + ((st+1)&1)*S_STG;
            #pragma unroll
            for (int l = 0; l < 2; l++) {
                int u = tid + l*256;
                int row = u >> 2, c8 = (u & 3)*8;
                uint32_t so = (uint32_t)(row*PAD + c8)*2;
                size_t go = (size_t)row*DIM + en + c8;
                cpa(bb + S_QH + so, Qh + go);
                cpa(bb + S_QL + so, Ql + go);
                cpa(bb + S_KH + so, Kh + go);
                cpa(bb + S_KL + so, Kl + go);
            }
            CPA_COMMIT;
        }
        uint32_t cb = smb + (st&1)*S_STG;
        #pragma unroll
        for (int ks = 0; ks < 32; ks += 16) {
            uint32_t ah[2][4], al[2][4];
            #pragma unroll
            for (int mf = 0; mf < 2; mf++) {
                ldsm4(ah[mf], addr_am(cb + S_QH, lane, wm*32 + mf*16, ks, PAD));
                ldsm4(al[mf], addr_am(cb + S_QL, lane, wm*32 + mf*16, ks, PAD));
            }
            uint32_t bh[4][4], bl[4][4];
            #pragma unroll
            for (int p = 0; p < 4; p++) {
                ldsm4(bh[p], addr_bn(cb + S_KH, lane, wn*64 + p*16, ks, PAD));
                ldsm4(bl[p], addr_bn(cb + S_KL, lane, wn*64 + p*16, ks, PAD));
            }
            #pragma unroll
            for (int nf = 0; nf < 8; nf++) {
                const uint32_t* pbh = &bh[nf>>1][(nf&1)*2];
                const uint32_t* pbl = &bl[nf>>1][(nf&1)*2];
                #pragma unroll
                for (int mf = 0; mf < 2; mf++) {
                    mma16816(accA[mf][nf], ah[mf], pbh);
                    mma16816(accA[mf][nf], ah[mf], pbl);
                    mma16816(accA[mf][nf], al[mf], pbh);
                }
            }
        }
    }

    // mask + decay, accumulate row sums
    #pragma unroll
    for (int mf = 0; mf < 2; mf++) {
        int i1 = wm*32 + mf*16 + gr, i2 = i1 + 8;
        float r1 = rowg[i1], r2 = rowg[i2];
        float rs1 = 0.f, rs2 = 0.f;
        #pragma unroll
        for (int nf = 0; nf < 8; nf++) {
            int j = wn*64 + nf*8 + tg*2;
            float cj0 = cw[j], cj1 = cw[j+1];
            accA[mf][nf][0] = (i1 >= j)   ? accA[mf][nf][0]*r1*cj0 : 0.f;
            accA[mf][nf][1] = (i1 >= j+1) ? accA[mf][nf][1]*r1*cj1 : 0.f;
            accA[mf][nf][2] = (i2 >= j)   ? accA[mf][nf][2]*r2*cj0 : 0.f;
            accA[mf][nf][3] = (i2 >= j+1) ? accA[mf][nf][3]*r2*cj1 : 0.f;
            rs1 += accA[mf][nf][0] + accA[mf][nf][1];
            rs2 += accA[mf][nf][2] + accA[mf][nf][3];
        }
        atomicAdd(&rsum[i1], rs1);
        atomicAdd(&rsum[i2], rs2);
    }
    __syncthreads();
    if (tid < CHK) {
        float d = 1.0f / fmaxf(fabsf(rsum[tid]), 1.0f);
        dv[tid] = d;
        g_dinv[b*SEQ + c0 + tid] = d;
    }
    __syncthreads();

    #pragma unroll
    for (int mf = 0; mf < 2; mf++) {
        int i1 = wm*32 + mf*16 + gr, i2 = i1 + 8;
        #pragma unroll
        for (int nf = 0; nf < 8; nf++) {
            int j = wn*64 + nf*8 + tg*2;
            float dj0 = dv[j], dj1 = dv[j+1];
            uint32_t lw;
            uint32_t hw = pack2(accA[mf][nf][0]*dj0, accA[mf][nf][1]*dj1, lw);
            *(uint32_t*)&g_Sh[(size_t)(blk*CHK + i1)*CHK + j] = hw;
            *(uint32_t*)&g_Sl[(size_t)(blk*CHK + i1)*CHK + j] = lw;
            hw = pack2(accA[mf][nf][2]*dj0, accA[mf][nf][3]*dj1, lw);
            *(uint32_t*)&g_Sh[(size_t)(blk*CHK + i2)*CHK + j] = hw;
            *(uint32_t*)&g_Sl[(size_t)(blk*CHK + i2)*CHK + j] = lw;
        }
    }
}

// ---------------- K5: chunk-local T (cp.async V, reg-prefetch K) ----------
#define T_KH 0
#define T_KL 8704
#define T_V(buf) (17408 + (buf)*17408)
#define SM_TLOC 52224
__global__ void __launch_bounds__(256,2) k_tloc() {
    extern __shared__ char sm[];
    __shared__ float w2[CHK];
    int tid = threadIdx.x, lane = tid & 31, warp = tid >> 5;
    int gr = lane >> 2, tg = lane & 3;
    int wm = warp >> 1, wn = warp & 1;
    int blk = blockIdx.x, b = blk >> 5, c = blk & 31, c0 = c*CHK;
    int d1t = blockIdx.y*128, d2t = blockIdx.z*128;
    uint32_t smb = smem_u32(sm);

    const __nv_bfloat16 *Kh = g_Kh + (size_t)(b*SEQ + c0)*DIM + d1t;
    const __nv_bfloat16 *Kl = g_Kl + (size_t)(b*SEQ + c0)*DIM + d1t;
    const __nv_bfloat16 *Vh = g_Vh + (size_t)(b*SEQ + c0)*DIM + d2t;
    const __nv_bfloat16 *Vl = g_Vl + (size_t)(b*SEQ + c0)*DIM + d2t;

    if (tid < CHK) {
        int gj = c0 + tid;
        w2[tid] = __expf((float)(127-tid)*logf(GAMMA)) * g_ic[gj]*INV16*g_dinv[b*SEQ+gj];
    }

    uint4 khr[2], klr[2];
    #pragma unroll
    for (int l = 0; l < 2; l++) {
        int u = tid + l*256;
        int row = u >> 4, c8 = (u & 15)*8;
        khr[l] = *(const uint4*)(Kh + (size_t)row*DIM + c8);
        klr[l] = *(const uint4*)(Kl + (size_t)row*DIM + c8);
    }
    #pragma unroll
    for (int l = 0; l < 2; l++) {
        int u = tid + l*256;
        int row = u >> 4, c8 = (u & 15)*8;
        uint32_t so = (uint32_t)(row*136 + c8)*2;
        cpa(smb + T_V(0) + so,        Vh + (size_t)row*DIM + c8);
        cpa(smb + T_V(0) + 8704 + so, Vl + (size_t)row*DIM + c8);
    }
    CPA_COMMIT;
    __syncthreads();   // w2 visible

    float acc[2][8][4] = {};

    for (int st = 0; st < 4; st++) {
        int j0 = st*32;
        CPA_WAIT0;
        __syncthreads();
        // STS wK (single buffer)
        #pragma unroll
        for (int l = 0; l < 2; l++) {
            int u = tid + l*256;
            int row = u >> 4, c8 = (u & 15)*8;
            float f[8]; load8r(f, khr[l], klr[l]);
            float w = w2[j0 + row];
            uint32_t hw[4], lw[4];
            #pragma unroll
            for (int i2 = 0; i2 < 4; i2++) hw[i2] = pack2(f[2*i2]*w, f[2*i2+1]*w, lw[i2]);
            *(uint4*)(sm + T_KH + (row*136 + c8)*2) = *(uint4*)hw;
            *(uint4*)(sm + T_KL + (row*136 + c8)*2) = *(uint4*)lw;
        }
        if (st < 3) {
            int jn = j0 + 32;
            #pragma unroll
            for (int l = 0; l < 2; l++) {
                int u = tid + l*256;
                int row = u >> 4, c8 = (u & 15)*8;
                uint32_t so = (uint32_t)(row*136 + c8)*2;
                cpa(smb + T_V((st+1)&1) + so,        Vh + (size_t)(jn+row)*DIM + c8);
                cpa(smb + T_V((st+1)&1) + 8704 + so, Vl + (size_t)(jn+row)*DIM + c8);
            }
            CPA_COMMIT;
        }
        __syncthreads();
        if (st < 3) {
            int jn = j0 + 32;
            #pragma unroll
            for (int l = 0; l < 2; l++) {
                int u = tid + l*256;
                int row = u >> 4, c8 = (u & 15)*8;
                khr[l] = *(const uint4*)(Kh + (size_t)(jn+row)*DIM + c8);
                klr[l] = *(const uint4*)(Kl + (size_t)(jn+row)*DIM + c8);
            }
        }
        uint32_t vb = smb + T_V(st&1);
        #pragma unroll
        for (int ks = 0; ks < 32; ks += 16) {
            uint32_t ah[2][4], al[2][4];
            #pragma unroll
            for (int mf = 0; mf < 2; mf++) {
                ldsm4t(ah[mf], aaddr_t(smb + T_KH, lane, wm*32 + mf*16, ks, 136));
                ldsm4t(al[mf], aaddr_t(smb + T_KL, lane, wm*32 + mf*16, ks, 136));
            }
            #pragma unroll
            for (int nfp = 0; nfp < 4; nfp++) {
                uint32_t bh[4], bl[4];
                ldsm4t(bh, baddr(vb, lane, ks, wn*64 + nfp*16, 136));
                ldsm4t(bl, baddr(vb + 8704, lane, ks, wn*64 + nfp*16, 136));
                #pragma unroll
                for (int mf = 0; mf < 2; mf++) {
                    mma16816(acc[mf][2*nfp],   ah[mf], bh);
                    mma16816(acc[mf][2*nfp+1], ah[mf], bh+2);
                    mma16816(acc[mf][2*nfp],   ah[mf], bl);
                    mma16816(acc[mf][2*nfp+1], ah[mf], bl+2);
                    mma16816(acc[mf][2*nfp],   al[mf], bh);
                    mma16816(acc[mf][2*nfp+1], al[mf], bh+2);
                }
            }
        }
    }
    #pragma unroll
    for (int mf = 0; mf < 2; mf++) {
        int d1 = d1t + wm*32 + mf*16 + gr;
        #pragma unroll
        for (int nf = 0; nf < 8; nf++) {
            int d2 = d2t + wn*64 + nf*8 + tg*2;
            *(float2*)&g_T[((size_t)blk*DIM + d1)*DIM + d2]     = make_float2(acc[mf][nf][0], acc[mf][nf][1]);
            *(float2*)&g_T[((size_t)blk*DIM + d1 + 8)*DIM + d2] = make_float2(acc[mf][nf][2], acc[mf][nf][3]);
        }
    }
}

// ---------------- K6: prefix of T -> bf16 hi/lo ----------------------------
__global__ void k_tpref() {
    int idx = blockIdx.x*256 + threadIdx.x;
    int b   = idx >> 16;
    int off = idx & 65535;
    float v[NCH];
    #pragma unroll
    for (int c = 0; c < NCH; c++) v[c] = g_T[(((size_t)(b*NCH + c)) << 16) + off];
    float gC = __expf(128.f*logf(GAMMA));
    float t = 0.f;
    #pragma unroll
    for (int c = 0; c < NCH; c++) {
        size_t p = (((size_t)(b*NCH + c)) << 16) + off;
        __nv_bfloat16 h = __float2bfloat16(t);
        g_Th[p] = h;
        g_Tl[p] = __float2bfloat16(t - __bfloat162float(h));
        t = t*gC + v[c];
    }
}

// ---------------- K7b: out = S@V + (g^{i+1} Q)@T ---------------------------
#define B_A(buf) ((buf)*20480)
#define B_B(buf) (40960 + (buf)*17408)
#define SM_KB 75776
__global__ void __launch_bounds__(256,2) k_B(float* __restrict__ out) {
    extern __shared__ char sm[];
    __shared__ float rowGn[CHK];
    int tid = threadIdx.x, lane = tid & 31, warp = tid >> 5;
    int gr = lane >> 2, tg = lane & 3;
    int wm = warp >> 1, wn = warp & 1;
    int blk = blockIdx.x, b = blk >> 5, c = blk & 31, c0 = c*CHK;
    int d0 = blockIdx.y * 128;
    uint32_t smb = smem_u32(sm);

    const __nv_bfloat16 *Sh = g_Sh + (size_t)blk*CHK*CHK;
    const __nv_bfloat16 *Sl = g_Sl + (size_t)blk*CHK*CHK;
    const __nv_bfloat16 *Vh = g_Vh + (size_t)(b*SEQ + c0)*DIM + d0;
    const __nv_bfloat16 *Vl = g_Vl + (size_t)(b*SEQ + c0)*DIM + d0;
    const __nv_bfloat16 *Qh = g_Qh + (size_t)(b*SEQ + c0)*DIM;
    const __nv_bfloat16 *Ql = g_Ql + (size_t)(b*SEQ + c0)*DIM;
    const __nv_bfloat16 *Th = g_Th + (size_t)blk*65536 + d0;
    const __nv_bfloat16 *Tl = g_Tl + (size_t)blk*65536 + d0;

    if (tid < CHK) rowGn[tid] = __expf((float)(tid+1) * logf(GAMMA));

    // B1 prologue: stage 0 (S + V)
    #pragma unroll
    for (int l = 0; l < 2; l++) {
        int u = tid + l*256;
        int row = u >> 2, c8 = (u & 3)*8;
        uint32_t so = (uint32_t)(row*PAD + c8)*2;
        cpa(smb + B_A(0) + so,         Sh + (size_t)row*CHK + c8);
        cpa(smb + B_A(0) + 10240 + so, Sl + (size_t)row*CHK + c8);
    }
    #pragma unroll
    for (int l = 0; l < 2; l++) {
        int u = tid + l*256;
        int row = u >> 4, c8 = (u & 15)*8;
        uint32_t so = (uint32_t)(row*136 + c8)*2;
        cpa(smb + B_B(0) + so,        Vh + (size_t)row*DIM + c8);
        cpa(smb + B_B(0) + 8704 + so, Vl + (size_t)row*DIM + c8);
    }
    CPA_COMMIT;
    __syncthreads();   // rowGn visible

    float acc[2][8][4] = {};

    // ---- B1: S @ V, 4 stages, fully cp.async ----
    for (int st = 0; st < 4; st++) {
        CPA_WAIT0;
        __syncthreads();
        if (st < 3) {
            int kn = (st+1)*32;
            uint32_t ab = smb + B_A((st+1)&1), bb = smb + B_B((st+1)&1);
            #pragma unroll
            for (int l = 0; l < 2; l++) {
                int u = tid + l*256;
                int row = u >> 2, c8 = (u & 3)*8;
                uint32_t so = (uint32_t)(row*PAD + c8)*2;
                cpa(ab + so,         Sh + (size_t)row*CHK + kn + c8);
                cpa(ab + 10240 + so, Sl + (size_t)row*CHK + kn + c8);
            }
            #pragma unroll
            for (int l = 0; l < 2; l++) {
                int u = tid + l*256;
                int row = u >> 4, c8 = (u & 15)*8;
                uint32_t so = (uint32_t)(row*136 + c8)*2;
                cpa(bb + so,        Vh + (size_t)(kn+row)*DIM + c8);
                cpa(bb + 8704 + so, Vl + (size_t)(kn+row)*DIM + c8);
            }
            CPA_COMMIT;
        }
        uint32_t ab = smb + B_A(st&1), bb = smb + B_B(st&1);
        #pragma unroll
        for (int ks = 0; ks < 32; ks += 16) {
            uint32_t ah[2][4], al[2][4];
            #pragma unroll
            for (int mf = 0; mf < 2; mf++) {
                ldsm4(ah[mf], addr_am(ab, lane, wm*32 + mf*16, ks, PAD));
                ldsm4(al[mf], addr_am(ab + 10240, lane, wm*32 + mf*16, ks, PAD));
            }
            #pragma unroll
            for (int nfp = 0; nfp < 4; nfp++) {
                uint32_t bh[4], bl[4];
                ldsm4t(bh, baddr(bb, lane, ks, wn*64 + nfp*16, 136));
                ldsm4t(bl, baddr(bb + 8704, lane, ks, wn*64 + nfp*16, 136));
                #pragma unroll
                for (int mf = 0; mf < 2; mf++) {
                    mma16816(acc[mf][2*nfp],   ah[mf], bh);
                    mma16816(acc[mf][2*nfp+1], ah[mf], bh+2);
                    mma16816(acc[mf][2*nfp],   ah[mf], bl);
                    mma16816(acc[mf][2*nfp+1], ah[mf], bl+2);
                    mma16816(acc[mf][2*nfp],   al[mf], bh);
                    mma16816(acc[mf][2*nfp+1], al[mf], bh+2);
                }
            }
        }
    }

    // ---- B2: (g^{i+1} Q) @ T_prefix, 8 stages ----
    uint4 qhr[2], qlr[2];
    #pragma unroll
    for (int l = 0; l < 2; l++) {
        int u = tid + l*256;
        int row = u >> 2, c8 = (u & 3)*8;
        qhr[l] = *(const uint4*)(Qh + (size_t)row*DIM + c8);
        qlr[l] = *(const uint4*)(Ql + (size_t)row*DIM + c8);
    }
    #pragma unroll
    for (int l = 0; l < 2; l++) {
        int u = tid + l*256;
        int row = u >> 4, c8 = (u & 15)*8;
        uint32_t so = (uint32_t)(row*136 + c8)*2;
        cpa(smb + B_B(0) + so,        Th + (size_t)row*DIM + c8);
        cpa(smb + B_B(0) + 8704 + so, Tl + (size_t)row*DIM + c8);
    }
    CPA_COMMIT;

    for (int st = 0; st < 8; st++) {
        CPA_WAIT0;
        __syncthreads();
        // STS scaled Q into A buf (st&1)
        uint32_t ab = smb + B_A(st&1);
        #pragma unroll
        for (int l = 0; l < 2; l++) {
            int u = tid + l*256;
            int row = u >> 2, c8 = (u & 3)*8;
            float f[8]; load8r(f, qhr[l], qlr[l]);
            float rG = rowGn[row];
            uint32_t hw[4], lw[4];
            #pragma unroll
            for (int i2 = 0; i2 < 4; i2++) hw[i2] = pack2(f[2*i2]*rG, f[2*i2+1]*rG, lw[i2]);
            *(uint4*)(sm + B_A(st&1) + (row*PAD + c8)*2)         = *(uint4*)hw;
            *(uint4*)(sm + B_A(st&1) + 10240 + (row*PAD + c8)*2) = *(uint4*)lw;
        }
        if (st < 7) {
            int en = (st+1)*32;
            uint32_t bb = smb + B_B((st+1)&1);
            #pragma unroll
            for (int l = 0; l < 2; l++) {
                int u = tid + l*256;
                int row = u >> 4, c8 = (u & 15)*8;
                uint32_t so = (uint32_t)(row*136 + c8)*2;
                cpa(bb + so,        Th + (size_t)(en+row)*DIM + c8);
                cpa(bb + 8704 + so, Tl + (size_t)(en+row)*DIM + c8);
            }
            CPA_COMMIT;
        }
        __syncthreads();
        if (st < 7) {
            int en = (st+1)*32;
            #pragma unroll
            for (int l = 0; l < 2; l++) {
                int u = tid + l*256;
                int row = u >> 2, c8 = (u & 3)*8;
                qhr[l] = *(const uint4*)(Qh + (size_t)row*DIM + en + c8);
                qlr[l] = *(const uint4*)(Ql + (size_t)row*DIM + en + c8);
            }
        }
        uint32_t bb = smb + B_B(st&1);
        #pragma unroll
        for (int ks = 0; ks < 32; ks += 16) {
            uint32_t ah[2][4], al[2][4];
            #pragma unroll
            for (int mf = 0; mf < 2; mf++) {
                ldsm4(ah[mf], addr_am(ab, lane, wm*32 + mf*16, ks, PAD));
                ldsm4(al[mf], addr_am(ab + 10240, lane, wm*32 + mf*16, ks, PAD));
            }
            #pragma unroll
            for (int nfp = 0; nfp < 4; nfp++) {
                uint32_t bh[4], bl[4];
                ldsm4t(bh, baddr(bb, lane, ks, wn*64 + nfp*16, 136));
                ldsm4t(bl, baddr(bb + 8704, lane, ks, wn*64 + nfp*16, 136));
                #pragma unroll
                for (int mf = 0; mf < 2; mf++) {
                    mma16816(acc[mf][2*nfp],   ah[mf], bh);
                    mma16816(acc[mf][2*nfp+1], ah[mf], bh+2);
                    mma16816(acc[mf][2*nfp],   ah[mf], bl);
                    mma16816(acc[mf][2*nfp+1], ah[mf], bl+2);
                    mma16816(acc[mf][2*nfp],   al[mf], bh);
                    mma16816(acc[mf][2*nfp+1], al[mf], bh+2);
                }
            }
        }
    }

    #pragma unroll
    for (int mf = 0; mf < 2; mf++) {
        int i1 = wm*32 + mf*16 + gr;
        #pragma unroll
        for (int nf = 0; nf < 8; nf++) {
            int n = d0 + wn*64 + nf*8 + tg*2;
            *(float2*)&out[(size_t)(b*SEQ + c0 + i1)*DIM + n]     = make_float2(acc[mf][nf][0], acc[mf][nf][1]);
            *(float2*)&out[(size_t)(b*SEQ + c0 + i1 + 8)*DIM + n] = make_float2(acc[mf][nf][2], acc[mf][nf][3]);
        }
    }
}

// -------------------------------------------------------------------------
extern "C" void kernel_launch(void* const* d_in, const int* in_sizes, int n_in,
                              void* d_out, int out_size) {
    const float* xq = (const float*)d_in[0];
    const float* xk = (const float*)d_in[1];
    const float* xv = (const float*)d_in[2];
    const float* Wq = (const float*)d_in[3];
    const float* bq = (const float*)d_in[4];
    const float* Wk = (const float*)d_in[5];
    const float* bk = (const float*)d_in[6];
    const float* Wv = (const float*)d_in[7];
    const float* bv = (const float*)d_in[8];
    float* out = (float*)d_out;

    static int once = 0;
    if (!once) {
        cudaFuncSetAttribute(k_proj_mma, cudaFuncAttributeMaxDynamicSharedMemorySize, SM_PROJ);
        cudaFuncSetAttribute(k_S,        cudaFuncAttributeMaxDynamicSharedMemorySize, SM_KS);
        cudaFuncSetAttribute(k_tloc,     cudaFuncAttributeMaxDynamicSharedMemorySize, SM_TLOC);
        cudaFuncSetAttribute(k_B,        cudaFuncAttributeMaxDynamicSharedMemorySize, SM_KB);
        once = 1;
    }

    k_prep  <<<dim3(DIM, 3), 256>>>(Wq, Wk, Wv);
    k_proj_mma<<<dim3(ROWS_TOT/128, DIM/128, 3), 256, SM_PROJ>>>(xq, xk, xv, bq, bk, bv);
    k_spref <<<BB*8, 32>>>();
    k_S     <<<BB*NCH, 256, SM_KS>>>();
    k_tloc  <<<dim3(BB*NCH, 2, 2), 256, SM_TLOC>>>();
    k_tpref <<<BB*DIM*DIM/256, 256>>>();
    k_B     <<<dim3(BB*NCH, 2), 256, SM_KB>>>(out);
}